// round 2
// baseline (speedup 1.0000x reference)
#include <cuda_runtime.h>
#include <math.h>

#define BZ 8
#define LQ 1024
#define D  512
#define NH 8
#define DH 64

// ---------------- scratch (device globals; no allocation allowed) ----------------
__device__ float g_h[BZ * LQ * D];        // 16 MB  h = transpose(query) [bz, Lq, d]
__device__ float g_Q[BZ * LQ * D];        // 16 MB
__device__ float g_K[BZ * LQ * D];        // 16 MB
__device__ float g_V[BZ * LQ * D];        // 16 MB
__device__ float g_norm[BZ * LQ];         // row norms of h (clamped at 1e-8)
__device__ unsigned char g_mask[(size_t)BZ * LQ * LQ];  // 8 MB, 1 = masked

// ---------------- K1: transpose query[Lq,bz,d] -> h[bz,Lq,d] ----------------
__global__ void k_transpose(const float* __restrict__ q) {
    int idx = blockIdx.x * blockDim.x + threadIdx.x;      // float4 index
    if (idx >= BZ * LQ * (D / 4)) return;
    int k4 = idx & 127;               // D/4 = 128
    int b  = (idx >> 7) & 7;
    int i  = idx >> 10;
    float4 v = ((const float4*)q)[idx];
    ((float4*)g_h)[(b * LQ + i) * (D / 4) + k4] = v;
}

// ---------------- K2: per-row norms of h ----------------
__global__ void k_norms() {
    int warp = (blockIdx.x * blockDim.x + threadIdx.x) >> 5;
    int lane = threadIdx.x & 31;
    if (warp >= BZ * LQ) return;
    const float* row = g_h + (size_t)warp * D;
    float s = 0.f;
    for (int k = lane; k < D; k += 32) { float v = row[k]; s += v * v; }
    #pragma unroll
    for (int o = 16; o; o >>= 1) s += __shfl_xor_sync(0xffffffffu, s, o);
    if (lane == 0) g_norm[warp] = fmaxf(sqrtf(s), 1e-8f);
}

// ---------------- K3: C[M,N] = A[M,K] * B[N,K]^T + bias[N] ----------------
// 128x128 tile, 256 threads, 8x8 micro-tile, k-panel 8, double buffered.
__global__ __launch_bounds__(256) void k_sgemm_nt(
    const float* __restrict__ A, const float* __restrict__ B,
    const float* __restrict__ bias, float* __restrict__ C,
    int M, int N, int K)
{
    __shared__ float As[2][8][132];
    __shared__ float Bs[2][8][132];
    int tid = threadIdx.x;
    int tx = tid & 15, ty = tid >> 4;
    int m0 = blockIdx.y * 128, n0 = blockIdx.x * 128;
    int ar = tid >> 1, ac = (tid & 1) * 4;   // each thread: one float4 of A, one of B
    const float* Ap = A + (size_t)(m0 + ar) * K + ac;
    const float* Bp = B + (size_t)(n0 + ar) * K + ac;

    float4 a4 = *(const float4*)Ap;
    float4 b4 = *(const float4*)Bp;
    As[0][ac+0][ar]=a4.x; As[0][ac+1][ar]=a4.y; As[0][ac+2][ar]=a4.z; As[0][ac+3][ar]=a4.w;
    Bs[0][ac+0][ar]=b4.x; Bs[0][ac+1][ar]=b4.y; Bs[0][ac+2][ar]=b4.z; Bs[0][ac+3][ar]=b4.w;
    __syncthreads();

    float acc[8][8] = {};
    int nP = K >> 3;
    int buf = 0;
    for (int p = 0; p < nP; p++) {
        if (p + 1 < nP) {
            a4 = *(const float4*)(Ap + (p + 1) * 8);
            b4 = *(const float4*)(Bp + (p + 1) * 8);
        }
        #pragma unroll
        for (int kk = 0; kk < 8; kk++) {
            float4 a0 = *(const float4*)&As[buf][kk][ty * 4];
            float4 a1 = *(const float4*)&As[buf][kk][64 + ty * 4];
            float4 b0 = *(const float4*)&Bs[buf][kk][tx * 4];
            float4 b1 = *(const float4*)&Bs[buf][kk][64 + tx * 4];
            float av[8] = {a0.x,a0.y,a0.z,a0.w,a1.x,a1.y,a1.z,a1.w};
            float bv[8] = {b0.x,b0.y,b0.z,b0.w,b1.x,b1.y,b1.z,b1.w};
            #pragma unroll
            for (int i = 0; i < 8; i++)
                #pragma unroll
                for (int j = 0; j < 8; j++) acc[i][j] += av[i] * bv[j];
        }
        if (p + 1 < nP) {
            buf ^= 1;
            As[buf][ac+0][ar]=a4.x; As[buf][ac+1][ar]=a4.y; As[buf][ac+2][ar]=a4.z; As[buf][ac+3][ar]=a4.w;
            Bs[buf][ac+0][ar]=b4.x; Bs[buf][ac+1][ar]=b4.y; Bs[buf][ac+2][ar]=b4.z; Bs[buf][ac+3][ar]=b4.w;
        }
        __syncthreads();
    }

    float4 bs0 = *(const float4*)&bias[n0 + tx * 4];
    float4 bs1 = *(const float4*)&bias[n0 + 64 + tx * 4];
    #pragma unroll
    for (int i = 0; i < 8; i++) {
        int m = m0 + ((i < 4) ? (ty * 4 + i) : (64 + ty * 4 + i - 4));
        float4 c0 = make_float4(acc[i][0]+bs0.x, acc[i][1]+bs0.y, acc[i][2]+bs0.z, acc[i][3]+bs0.w);
        float4 c1 = make_float4(acc[i][4]+bs1.x, acc[i][5]+bs1.y, acc[i][6]+bs1.z, acc[i][7]+bs1.w);
        *(float4*)&C[(size_t)m * N + n0 + tx * 4] = c0;
        *(float4*)&C[(size_t)m * N + n0 + 64 + tx * 4] = c1;
    }
}

// ---------------- K4: mask = f(iou(segments), cos(h,h)) ----------------
// 128x128 Gram tile per block with fused mask epilogue. Grid (Lq/128, Lq/128, bz).
__global__ __launch_bounds__(256) void k_mask(const float* __restrict__ seg) {
    __shared__ float As[2][8][132];
    __shared__ float Bs[2][8][132];
    __shared__ float si[128], ei[128], li[128], ni[128];
    __shared__ float sj[128], ej[128], lj[128], nj[128];
    int b  = blockIdx.z;
    int i0 = blockIdx.y * 128, j0 = blockIdx.x * 128;
    int tid = threadIdx.x, tx = tid & 15, ty = tid >> 4;

    if (tid < 128) {
        int gi = b * LQ + i0 + tid;
        float c = seg[gi * 2], l = seg[gi * 2 + 1];
        si[tid] = c - 0.5f * l; ei[tid] = c + 0.5f * l; li[tid] = l;
        ni[tid] = g_norm[gi];
    } else {
        int t = tid - 128;
        int gj = b * LQ + j0 + t;
        float c = seg[gj * 2], l = seg[gj * 2 + 1];
        sj[t] = c - 0.5f * l; ej[t] = c + 0.5f * l; lj[t] = l;
        nj[t] = g_norm[gj];
    }

    const float* A = g_h + (size_t)b * LQ * D;
    int ar = tid >> 1, ac = (tid & 1) * 4;
    const float* Ap = A + (size_t)(i0 + ar) * D + ac;
    const float* Bp = A + (size_t)(j0 + ar) * D + ac;

    float4 a4 = *(const float4*)Ap;
    float4 b4 = *(const float4*)Bp;
    As[0][ac+0][ar]=a4.x; As[0][ac+1][ar]=a4.y; As[0][ac+2][ar]=a4.z; As[0][ac+3][ar]=a4.w;
    Bs[0][ac+0][ar]=b4.x; Bs[0][ac+1][ar]=b4.y; Bs[0][ac+2][ar]=b4.z; Bs[0][ac+3][ar]=b4.w;
    __syncthreads();

    float acc[8][8] = {};
    int nP = D >> 3;
    int buf = 0;
    for (int p = 0; p < nP; p++) {
        if (p + 1 < nP) {
            a4 = *(const float4*)(Ap + (p + 1) * 8);
            b4 = *(const float4*)(Bp + (p + 1) * 8);
        }
        #pragma unroll
        for (int kk = 0; kk < 8; kk++) {
            float4 a0 = *(const float4*)&As[buf][kk][ty * 4];
            float4 a1 = *(const float4*)&As[buf][kk][64 + ty * 4];
            float4 b0 = *(const float4*)&Bs[buf][kk][tx * 4];
            float4 b1 = *(const float4*)&Bs[buf][kk][64 + tx * 4];
            float av[8] = {a0.x,a0.y,a0.z,a0.w,a1.x,a1.y,a1.z,a1.w};
            float bv[8] = {b0.x,b0.y,b0.z,b0.w,b1.x,b1.y,b1.z,b1.w};
            #pragma unroll
            for (int i = 0; i < 8; i++)
                #pragma unroll
                for (int j = 0; j < 8; j++) acc[i][j] += av[i] * bv[j];
        }
        if (p + 1 < nP) {
            buf ^= 1;
            As[buf][ac+0][ar]=a4.x; As[buf][ac+1][ar]=a4.y; As[buf][ac+2][ar]=a4.z; As[buf][ac+3][ar]=a4.w;
            Bs[buf][ac+0][ar]=b4.x; Bs[buf][ac+1][ar]=b4.y; Bs[buf][ac+2][ar]=b4.z; Bs[buf][ac+3][ar]=b4.w;
        }
        __syncthreads();
    }

    #pragma unroll
    for (int i = 0; i < 8; i++) {
        int ii = (i < 4) ? (ty * 4 + i) : (64 + ty * 4 + i - 4);
        int gi = i0 + ii;
        unsigned char mb[8];
        #pragma unroll
        for (int j = 0; j < 8; j++) {
            int jj = (j < 4) ? (tx * 4 + j) : (64 + tx * 4 + j - 4);
            int gj = j0 + jj;
            float cosv  = acc[i][j] / (ni[ii] * nj[jj]);
            float inter = fmaxf(fminf(ei[ii], ej[jj]) - fmaxf(si[ii], sj[jj]), 0.f);
            float uni   = li[ii] + lj[jj] - inter;
            float iou   = inter / uni;
            bool masked = (cosv <= 0.2f) || (iou > 0.2f && gi != gj);
            mb[j] = masked ? 1 : 0;
        }
        unsigned char* mp = g_mask + ((size_t)b * LQ + gi) * LQ;
        *(uchar4*)&mp[j0 + tx * 4]      = make_uchar4(mb[0], mb[1], mb[2], mb[3]);
        *(uchar4*)&mp[j0 + 64 + tx * 4] = make_uchar4(mb[4], mb[5], mb[6], mb[7]);
    }
}

// ---------------- K5: flash attention + residual + output transpose ----------------
// Br=128 query rows, Bc=64 keys per tile. 256 threads, 8x4 micro-tile.
// Online softmax with -1e30 sentinel (diagonal always unmasked; junk wiped by rescale).
__global__ __launch_bounds__(256) void k_attn(float* __restrict__ out) {
    extern __shared__ float sm[];
    float* Qt   = sm;                    // [64][132] k-major, i contiguous
    float* Kt   = Qt + 64 * 132;         // [64][68]  k-major, j contiguous
    float* Vs   = Kt + 64 * 68;          // [64][68]  j-major, n contiguous
    float* Ps   = Vs + 64 * 68;          // [128][68] i-major scores/probs
    float* mrow = Ps + 128 * 68;
    float* lrow = mrow + 128;
    float* srow = lrow + 128;

    int i0 = blockIdx.x * 128, head = blockIdx.y, b = blockIdx.z;
    int tid = threadIdx.x, tx = tid & 15, ty = tid >> 4;
    const size_t base = (size_t)b * LQ * D + head * DH;

    // load Q tile, transposed to k-major
    for (int t = tid; t < 2048; t += 256) {
        int r = t >> 4, kg = (t & 15) * 4;
        float4 v = *(const float4*)&g_Q[base + (size_t)(i0 + r) * D + kg];
        Qt[(kg + 0) * 132 + r] = v.x;
        Qt[(kg + 1) * 132 + r] = v.y;
        Qt[(kg + 2) * 132 + r] = v.z;
        Qt[(kg + 3) * 132 + r] = v.w;
    }
    if (tid < 128) { mrow[tid] = -1e30f; lrow[tid] = 0.f; }
    float O[8][4] = {};
    __syncthreads();

    for (int j0 = 0; j0 < LQ; j0 += 64) {
        // load K (transposed) and V tiles
        for (int t = tid; t < 1024; t += 256) {
            int c = t >> 4, kg = (t & 15) * 4;
            float4 kv = *(const float4*)&g_K[base + (size_t)(j0 + c) * D + kg];
            Kt[(kg + 0) * 68 + c] = kv.x;
            Kt[(kg + 1) * 68 + c] = kv.y;
            Kt[(kg + 2) * 68 + c] = kv.z;
            Kt[(kg + 3) * 68 + c] = kv.w;
            float4 vv = *(const float4*)&g_V[base + (size_t)(j0 + c) * D + kg];
            *(float4*)&Vs[c * 68 + kg] = vv;
        }
        __syncthreads();

        // S = Q K^T (8x4 micro-tile)
        float acc[8][4] = {};
        #pragma unroll 8
        for (int k = 0; k < 64; k++) {
            float4 a0 = *(const float4*)&Qt[k * 132 + ty * 4];
            float4 a1 = *(const float4*)&Qt[k * 132 + 64 + ty * 4];
            float4 bq = *(const float4*)&Kt[k * 68 + tx * 4];
            float av[8] = {a0.x,a0.y,a0.z,a0.w,a1.x,a1.y,a1.z,a1.w};
            float bv[4] = {bq.x,bq.y,bq.z,bq.w};
            #pragma unroll
            for (int i = 0; i < 8; i++)
                #pragma unroll
                for (int j = 0; j < 4; j++) acc[i][j] += av[i] * bv[j];
        }

        // mask + scale, write row-major Ps
        const unsigned char* mp = g_mask + ((size_t)b * LQ + i0) * LQ + j0;
        #pragma unroll
        for (int i = 0; i < 8; i++) {
            int ii = (i < 4) ? (ty * 4 + i) : (64 + ty * 4 + i - 4);
            uchar4 m4 = *(const uchar4*)&mp[(size_t)ii * LQ + tx * 4];
            float4 s4;
            s4.x = m4.x ? -1e30f : acc[i][0] * 0.125f;
            s4.y = m4.y ? -1e30f : acc[i][1] * 0.125f;
            s4.z = m4.z ? -1e30f : acc[i][2] * 0.125f;
            s4.w = m4.w ? -1e30f : acc[i][3] * 0.125f;
            *(float4*)&Ps[ii * 68 + tx * 4] = s4;
        }
        __syncthreads();

        // online softmax: one thread per query row
        if (tid < 128) {
            float m_old = mrow[tid], mx = m_old;
            float* srp = Ps + tid * 68;
            #pragma unroll 8
            for (int c = 0; c < 64; c++) mx = fmaxf(mx, srp[c]);
            float sc = __expf(m_old - mx);
            float sum = 0.f;
            #pragma unroll 8
            for (int c = 0; c < 64; c++) {
                float p = __expf(srp[c] - mx);
                srp[c] = p;
                sum += p;
            }
            lrow[tid] = lrow[tid] * sc + sum;
            mrow[tid] = mx;
            srow[tid] = sc;
        }
        __syncthreads();

        // rescale O; O += P @ V (p-loads are warp broadcasts)
        float scs[8];
        #pragma unroll
        for (int i = 0; i < 8; i++) {
            int ii = (i < 4) ? (ty * 4 + i) : (64 + ty * 4 + i - 4);
            scs[i] = srow[ii];
        }
        #pragma unroll
        for (int i = 0; i < 8; i++)
            #pragma unroll
            for (int j = 0; j < 4; j++) O[i][j] *= scs[i];
        #pragma unroll 8
        for (int jj = 0; jj < 64; jj++) {
            float4 vv = *(const float4*)&Vs[jj * 68 + tx * 4];
            float bv[4] = {vv.x, vv.y, vv.z, vv.w};
            float pv[8];
            #pragma unroll
            for (int i = 0; i < 8; i++) {
                int ii = (i < 4) ? (ty * 4 + i) : (64 + ty * 4 + i - 4);
                pv[i] = Ps[ii * 68 + jj];
            }
            #pragma unroll
            for (int i = 0; i < 8; i++)
                #pragma unroll
                for (int j = 0; j < 4; j++) O[i][j] += pv[i] * bv[j];
        }
        __syncthreads();
    }

    // epilogue: out[Lq, bz, d] = O/l + h
    #pragma unroll
    for (int i = 0; i < 8; i++) {
        int ii = (i < 4) ? (ty * 4 + i) : (64 + ty * 4 + i - 4);
        int gi = i0 + ii;
        float inv_l = 1.f / lrow[ii];
        float4 hv = *(const float4*)&g_h[((size_t)b * LQ + gi) * D + head * DH + tx * 4];
        float4 o;
        o.x = O[i][0] * inv_l + hv.x;
        o.y = O[i][1] * inv_l + hv.y;
        o.z = O[i][2] * inv_l + hv.z;
        o.w = O[i][3] * inv_l + hv.w;
        *(float4*)&out[((size_t)gi * BZ + b) * D + head * DH + tx * 4] = o;
    }
}

// ---------------- host ----------------
extern "C" void kernel_launch(void* const* d_in, const int* in_sizes, int n_in,
                              void* d_out, int out_size) {
    const float* query = (const float*)d_in[0];
    const float* seg   = (const float*)d_in[1];
    const float* Wq    = (const float*)d_in[2];
    const float* bq    = (const float*)d_in[3];
    const float* Wk    = (const float*)d_in[4];
    const float* bk    = (const float*)d_in[5];
    const float* Wv    = (const float*)d_in[6];
    const float* bv    = (const float*)d_in[7];
    float* out = (float*)d_out;

    float *hp, *qp, *kp, *vp;
    cudaGetSymbolAddress((void**)&hp, g_h);
    cudaGetSymbolAddress((void**)&qp, g_Q);
    cudaGetSymbolAddress((void**)&kp, g_K);
    cudaGetSymbolAddress((void**)&vp, g_V);

    k_transpose<<<(BZ * LQ * (D / 4) + 255) / 256, 256>>>(query);
    k_norms<<<(BZ * LQ * 32) / 256, 256>>>();

    dim3 gg(D / 128, BZ * LQ / 128);   // (4, 64)
    k_sgemm_nt<<<gg, 256>>>(hp, Wq, bq, qp, BZ * LQ, D, D);
    k_sgemm_nt<<<gg, 256>>>(hp, Wk, bk, kp, BZ * LQ, D, D);
    k_sgemm_nt<<<gg, 256>>>(hp, Wv, bv, vp, BZ * LQ, D, D);

    dim3 gm(LQ / 128, LQ / 128, BZ);   // (8, 8, 8)
    k_mask<<<gm, 256>>>(seg);

    int smem = (64 * 132 + 64 * 68 + 64 * 68 + 128 * 68 + 3 * 128) * (int)sizeof(float);
    cudaFuncSetAttribute(k_attn, cudaFuncAttributeMaxDynamicSharedMemorySize, smem);
    dim3 ga(LQ / 128, NH, BZ);         // (8, 8, 8)
    k_attn<<<ga, 256, smem>>>(out);
}

// round 3
// speedup vs baseline: 2.1225x; 2.1225x over previous
#include <cuda_runtime.h>
#include <stdint.h>
#include <math.h>

#define BZ 8
#define LQ 1024
#define D  512
#define NH 8
#define DH 64

// ---------------- scratch ----------------
__device__ float g_h[BZ * LQ * D];
__device__ float g_Q[BZ * LQ * D];
__device__ float g_K[BZ * LQ * D];
__device__ float g_V[BZ * LQ * D];
__device__ float g_norm[BZ * LQ];
__device__ unsigned char g_mask[(size_t)BZ * LQ * LQ];  // 1 = masked

// ---------------- tf32 helpers ----------------
__device__ __forceinline__ uint32_t f2tf(float f) {
    uint32_t u;
    asm("cvt.rna.tf32.f32 %0, %1;" : "=r"(u) : "f"(f));
    return u;
}
__device__ __forceinline__ void mma8(float* d, const uint32_t* a, const uint32_t* b) {
    asm volatile(
        "mma.sync.aligned.m16n8k8.row.col.f32.tf32.tf32.f32 "
        "{%0,%1,%2,%3},{%4,%5,%6,%7},{%8,%9},{%0,%1,%2,%3};\n"
        : "+f"(d[0]), "+f"(d[1]), "+f"(d[2]), "+f"(d[3])
        : "r"(a[0]), "r"(a[1]), "r"(a[2]), "r"(a[3]), "r"(b[0]), "r"(b[1]));
}

// ---------------- K1: transpose query[Lq,bz,d] -> h[bz,Lq,d] ----------------
__global__ void k_transpose(const float* __restrict__ q) {
    int idx = blockIdx.x * blockDim.x + threadIdx.x;
    if (idx >= BZ * LQ * (D / 4)) return;
    int k4 = idx & 127;
    int b  = (idx >> 7) & 7;
    int i  = idx >> 10;
    float4 v = ((const float4*)q)[idx];
    ((float4*)g_h)[(b * LQ + i) * (D / 4) + k4] = v;
}

// ---------------- K2: row norms ----------------
__global__ void k_norms() {
    int warp = (blockIdx.x * blockDim.x + threadIdx.x) >> 5;
    int lane = threadIdx.x & 31;
    if (warp >= BZ * LQ) return;
    const float* row = g_h + (size_t)warp * D;
    float s = 0.f;
    for (int k = lane; k < D; k += 32) { float v = row[k]; s += v * v; }
    #pragma unroll
    for (int o = 16; o; o >>= 1) s += __shfl_xor_sync(0xffffffffu, s, o);
    if (lane == 0) g_norm[warp] = fmaxf(sqrtf(s), 1e-8f);
}

// ---------------- K3: tf32 GEMM  C[M,N] = A[M,K] B[N,K]^T + bias ----------------
// 128x128 tile, 8 warps (2x4), warp tile 64x32, k-panel 16, double buffered.
#define KP 20
__global__ __launch_bounds__(256) void k_gemm(
    const float* __restrict__ A, const float* __restrict__ B,
    const float* __restrict__ bias, float* __restrict__ C,
    int M, int N, int K)
{
    __shared__ uint32_t As[2][128][KP];
    __shared__ uint32_t Bs[2][128][KP];
    int tid = threadIdx.x, lane = tid & 31, wid = tid >> 5;
    int g = lane >> 2, q = lane & 3;
    int wm = wid >> 2, wn = wid & 3;                 // 2 x 4 warp grid
    int m0 = blockIdx.y * 128, n0 = blockIdx.x * 128;

    int lrow = tid >> 1, lc = (tid & 1) * 8;         // each thread: 2 float4 per matrix
    const float* Ap = A + (size_t)(m0 + lrow) * K + lc;
    const float* Bp = B + (size_t)(n0 + lrow) * K + lc;

    float4 a0r = *(const float4*)Ap, a1r = *(const float4*)(Ap + 4);
    float4 b0r = *(const float4*)Bp, b1r = *(const float4*)(Bp + 4);
    {
        uint32_t* d = &As[0][lrow][lc];
        d[0]=f2tf(a0r.x); d[1]=f2tf(a0r.y); d[2]=f2tf(a0r.z); d[3]=f2tf(a0r.w);
        d[4]=f2tf(a1r.x); d[5]=f2tf(a1r.y); d[6]=f2tf(a1r.z); d[7]=f2tf(a1r.w);
        uint32_t* e = &Bs[0][lrow][lc];
        e[0]=f2tf(b0r.x); e[1]=f2tf(b0r.y); e[2]=f2tf(b0r.z); e[3]=f2tf(b0r.w);
        e[4]=f2tf(b1r.x); e[5]=f2tf(b1r.y); e[6]=f2tf(b1r.z); e[7]=f2tf(b1r.w);
    }
    __syncthreads();

    float acc[4][4][4] = {};
    int nP = K / 16, buf = 0;
    for (int p = 0; p < nP; p++) {
        if (p + 1 < nP) {
            const float* Ap2 = Ap + (p + 1) * 16;
            const float* Bp2 = Bp + (p + 1) * 16;
            a0r = *(const float4*)Ap2; a1r = *(const float4*)(Ap2 + 4);
            b0r = *(const float4*)Bp2; b1r = *(const float4*)(Bp2 + 4);
        }
        #pragma unroll
        for (int ks = 0; ks < 2; ks++) {
            int k8 = ks * 8;
            uint32_t af[4][4], bf[4][2];
            #pragma unroll
            for (int mt = 0; mt < 4; mt++) {
                int mb = wm * 64 + mt * 16;
                af[mt][0] = As[buf][mb + g][k8 + q];
                af[mt][1] = As[buf][mb + g + 8][k8 + q];
                af[mt][2] = As[buf][mb + g][k8 + q + 4];
                af[mt][3] = As[buf][mb + g + 8][k8 + q + 4];
            }
            #pragma unroll
            for (int nt = 0; nt < 4; nt++) {
                int nb = wn * 32 + nt * 8 + g;
                bf[nt][0] = Bs[buf][nb][k8 + q];
                bf[nt][1] = Bs[buf][nb][k8 + q + 4];
            }
            #pragma unroll
            for (int mt = 0; mt < 4; mt++)
                #pragma unroll
                for (int nt = 0; nt < 4; nt++) mma8(acc[mt][nt], af[mt], bf[nt]);
        }
        if (p + 1 < nP) {
            int nb = buf ^ 1;
            uint32_t* d = &As[nb][lrow][lc];
            d[0]=f2tf(a0r.x); d[1]=f2tf(a0r.y); d[2]=f2tf(a0r.z); d[3]=f2tf(a0r.w);
            d[4]=f2tf(a1r.x); d[5]=f2tf(a1r.y); d[6]=f2tf(a1r.z); d[7]=f2tf(a1r.w);
            uint32_t* e = &Bs[nb][lrow][lc];
            e[0]=f2tf(b0r.x); e[1]=f2tf(b0r.y); e[2]=f2tf(b0r.z); e[3]=f2tf(b0r.w);
            e[4]=f2tf(b1r.x); e[5]=f2tf(b1r.y); e[6]=f2tf(b1r.z); e[7]=f2tf(b1r.w);
            buf = nb;
        }
        __syncthreads();
    }

    #pragma unroll
    for (int mt = 0; mt < 4; mt++)
        #pragma unroll
        for (int h2 = 0; h2 < 2; h2++) {
            int m = m0 + wm * 64 + mt * 16 + g + h2 * 8;
            #pragma unroll
            for (int nt = 0; nt < 4; nt++) {
                int n = n0 + wn * 32 + nt * 8 + 2 * q;
                float2 v;
                v.x = acc[mt][nt][h2 * 2 + 0] + bias[n];
                v.y = acc[mt][nt][h2 * 2 + 1] + bias[n + 1];
                *(float2*)&C[(size_t)m * N + n] = v;
            }
        }
}

// ---------------- K4: mask via hi/lo-split tf32 Gram (fp32-accurate) ----------------
__global__ __launch_bounds__(256) void k_mask(const float* __restrict__ seg) {
    __shared__ uint32_t Ah[2][128][KP], Al[2][128][KP];
    __shared__ uint32_t Bh[2][128][KP], Bl[2][128][KP];
    __shared__ float si[128], ei[128], li[128], ni[128];
    __shared__ float sj[128], ej[128], lj[128], nj[128];
    int b = blockIdx.z;
    int i0 = blockIdx.y * 128, j0 = blockIdx.x * 128;
    int tid = threadIdx.x, lane = tid & 31, wid = tid >> 5;
    int g = lane >> 2, q = lane & 3;
    int wm = wid >> 2, wn = wid & 3;

    if (tid < 128) {
        int gi = b * LQ + i0 + tid;
        float c = seg[gi * 2], l = seg[gi * 2 + 1];
        si[tid] = c - 0.5f * l; ei[tid] = c + 0.5f * l; li[tid] = l;
        ni[tid] = g_norm[gi];
    } else {
        int t = tid - 128;
        int gj = b * LQ + j0 + t;
        float c = seg[gj * 2], l = seg[gj * 2 + 1];
        sj[t] = c - 0.5f * l; ej[t] = c + 0.5f * l; lj[t] = l;
        nj[t] = g_norm[gj];
    }

    const float* Abase = g_h + (size_t)b * LQ * D;
    int lrow = tid >> 1, lc = (tid & 1) * 8;
    const float* Ap = Abase + (size_t)(i0 + lrow) * D + lc;
    const float* Bp = Abase + (size_t)(j0 + lrow) * D + lc;

    float av[8], bv[8];
    {
        float4 x = *(const float4*)Ap, y = *(const float4*)(Ap + 4);
        av[0]=x.x; av[1]=x.y; av[2]=x.z; av[3]=x.w; av[4]=y.x; av[5]=y.y; av[6]=y.z; av[7]=y.w;
        x = *(const float4*)Bp; y = *(const float4*)(Bp + 4);
        bv[0]=x.x; bv[1]=x.y; bv[2]=x.z; bv[3]=x.w; bv[4]=y.x; bv[5]=y.y; bv[6]=y.z; bv[7]=y.w;
    }
    #pragma unroll
    for (int t = 0; t < 8; t++) {
        uint32_t h = f2tf(av[t]);
        Ah[0][lrow][lc + t] = h;
        Al[0][lrow][lc + t] = f2tf(av[t] - __uint_as_float(h));
        h = f2tf(bv[t]);
        Bh[0][lrow][lc + t] = h;
        Bl[0][lrow][lc + t] = f2tf(bv[t] - __uint_as_float(h));
    }
    __syncthreads();

    float acc[4][4][4] = {};
    int nP = D / 16, buf = 0;
    for (int p = 0; p < nP; p++) {
        if (p + 1 < nP) {
            const float* Ap2 = Ap + (p + 1) * 16;
            const float* Bp2 = Bp + (p + 1) * 16;
            float4 x = *(const float4*)Ap2, y = *(const float4*)(Ap2 + 4);
            av[0]=x.x; av[1]=x.y; av[2]=x.z; av[3]=x.w; av[4]=y.x; av[5]=y.y; av[6]=y.z; av[7]=y.w;
            x = *(const float4*)Bp2; y = *(const float4*)(Bp2 + 4);
            bv[0]=x.x; bv[1]=x.y; bv[2]=x.z; bv[3]=x.w; bv[4]=y.x; bv[5]=y.y; bv[6]=y.z; bv[7]=y.w;
        }
        #pragma unroll
        for (int ks = 0; ks < 2; ks++) {
            int k8 = ks * 8;
            uint32_t ah[4][4], al[4][4], bh[4][2], bl[4][2];
            #pragma unroll
            for (int mt = 0; mt < 4; mt++) {
                int mb = wm * 64 + mt * 16;
                ah[mt][0] = Ah[buf][mb + g][k8 + q];
                ah[mt][1] = Ah[buf][mb + g + 8][k8 + q];
                ah[mt][2] = Ah[buf][mb + g][k8 + q + 4];
                ah[mt][3] = Ah[buf][mb + g + 8][k8 + q + 4];
                al[mt][0] = Al[buf][mb + g][k8 + q];
                al[mt][1] = Al[buf][mb + g + 8][k8 + q];
                al[mt][2] = Al[buf][mb + g][k8 + q + 4];
                al[mt][3] = Al[buf][mb + g + 8][k8 + q + 4];
            }
            #pragma unroll
            for (int nt = 0; nt < 4; nt++) {
                int nb = wn * 32 + nt * 8 + g;
                bh[nt][0] = Bh[buf][nb][k8 + q];
                bh[nt][1] = Bh[buf][nb][k8 + q + 4];
                bl[nt][0] = Bl[buf][nb][k8 + q];
                bl[nt][1] = Bl[buf][nb][k8 + q + 4];
            }
            #pragma unroll
            for (int mt = 0; mt < 4; mt++)
                #pragma unroll
                for (int nt = 0; nt < 4; nt++) {
                    mma8(acc[mt][nt], ah[mt], bh[nt]);
                    mma8(acc[mt][nt], ah[mt], bl[nt]);
                    mma8(acc[mt][nt], al[mt], bh[nt]);
                }
        }
        if (p + 1 < nP) {
            int nb = buf ^ 1;
            #pragma unroll
            for (int t = 0; t < 8; t++) {
                uint32_t h = f2tf(av[t]);
                Ah[nb][lrow][lc + t] = h;
                Al[nb][lrow][lc + t] = f2tf(av[t] - __uint_as_float(h));
                h = f2tf(bv[t]);
                Bh[nb][lrow][lc + t] = h;
                Bl[nb][lrow][lc + t] = f2tf(bv[t] - __uint_as_float(h));
            }
            buf = nb;
        }
        __syncthreads();
    }

    #pragma unroll
    for (int mt = 0; mt < 4; mt++)
        #pragma unroll
        for (int h2 = 0; h2 < 2; h2++) {
            int ii = wm * 64 + mt * 16 + g + h2 * 8;
            int gi = i0 + ii;
            unsigned char* mp = g_mask + ((size_t)b * LQ + gi) * LQ + j0;
            #pragma unroll
            for (int nt = 0; nt < 4; nt++) {
                int jc = wn * 32 + nt * 8 + 2 * q;
                uchar2 r;
                #pragma unroll
                for (int e = 0; e < 2; e++) {
                    int jj = jc + e, gj = j0 + jj;
                    float cosv  = acc[mt][nt][h2 * 2 + e] / (ni[ii] * nj[jj]);
                    float inter = fmaxf(fminf(ei[ii], ej[jj]) - fmaxf(si[ii], sj[jj]), 0.f);
                    float uni   = li[ii] + lj[jj] - inter;
                    float iou   = inter / uni;
                    bool masked = (cosv <= 0.2f) || (iou > 0.2f && gi != gj);
                    if (e == 0) r.x = masked ? 1 : 0; else r.y = masked ? 1 : 0;
                }
                *(uchar2*)&mp[jc] = r;
            }
        }
}

// ---------------- K5: tensor-core flash attention ----------------
// Block: (b, head, 128 query rows). 8 warps (2m x 4n). Bc = 64 keys/step.
// smem floats: Qs[128][68] tf32 | Ks[64][68] tf32 | Vs[64][68] tf32 |
//              Ps[128][68] f32->tf32 | mrow/lrow/srow[128]
#define ATP 68
__global__ __launch_bounds__(256) void k_attn(float* __restrict__ out) {
    extern __shared__ float sm[];
    uint32_t* Qs = (uint32_t*)sm;                 // 128*68
    uint32_t* Ks = Qs + 128 * ATP;                // 64*68
    uint32_t* Vs = Ks + 64 * ATP;                 // 64*68
    float*    Ps = (float*)(Vs + 64 * ATP);       // 128*68
    uint32_t* Pu = (uint32_t*)Ps;
    float* mrow = Ps + 128 * ATP;
    float* lrow = mrow + 128;
    float* srow = lrow + 128;

    int i0 = blockIdx.x * 128, head = blockIdx.y, b = blockIdx.z;
    int tid = threadIdx.x, lane = tid & 31, wid = tid >> 5;
    int g = lane >> 2, q = lane & 3;
    int wm = wid >> 2, wn = wid & 3;             // 2 x 4
    const size_t base = (size_t)b * LQ * D + head * DH;

    // load Q tile (tf32, row-major stride 68)
    #pragma unroll
    for (int s = 0; s < 8; s++) {
        int f = tid + s * 256;
        int r = f >> 4, c4 = (f & 15) << 2;
        float4 v = *(const float4*)&g_Q[base + (size_t)(i0 + r) * D + c4];
        uint32_t* d = &Qs[r * ATP + c4];
        d[0] = f2tf(v.x); d[1] = f2tf(v.y); d[2] = f2tf(v.z); d[3] = f2tf(v.w);
    }
    if (tid < 128) { mrow[tid] = -1e30f; lrow[tid] = 0.f; }
    float O[4][2][4] = {};
    __syncthreads();

    for (int j0 = 0; j0 < LQ; j0 += 64) {
        // load K, V tiles (row-major [key][dh], tf32)
        #pragma unroll
        for (int s = 0; s < 4; s++) {
            int f = tid + s * 256;
            int r = f >> 4, c4 = (f & 15) << 2;
            size_t ga = base + (size_t)(j0 + r) * D + c4;
            float4 kv = *(const float4*)&g_K[ga];
            uint32_t* d = &Ks[r * ATP + c4];
            d[0] = f2tf(kv.x); d[1] = f2tf(kv.y); d[2] = f2tf(kv.z); d[3] = f2tf(kv.w);
            float4 vv = *(const float4*)&g_V[ga];
            uint32_t* e = &Vs[r * ATP + c4];
            e[0] = f2tf(vv.x); e[1] = f2tf(vv.y); e[2] = f2tf(vv.z); e[3] = f2tf(vv.w);
        }
        __syncthreads();

        // S = Q K^T : M=128, N=64 keys, K=64
        float S[4][2][4] = {};
        #pragma unroll
        for (int ks = 0; ks < 8; ks++) {
            int k8 = ks * 8;
            uint32_t af[4][4], bf[2][2];
            #pragma unroll
            for (int mt = 0; mt < 4; mt++) {
                int mb = wm * 64 + mt * 16;
                af[mt][0] = Qs[(mb + g) * ATP + k8 + q];
                af[mt][1] = Qs[(mb + g + 8) * ATP + k8 + q];
                af[mt][2] = Qs[(mb + g) * ATP + k8 + q + 4];
                af[mt][3] = Qs[(mb + g + 8) * ATP + k8 + q + 4];
            }
            #pragma unroll
            for (int nt = 0; nt < 2; nt++) {
                int nb = wn * 16 + nt * 8 + g;
                bf[nt][0] = Ks[nb * ATP + k8 + q];
                bf[nt][1] = Ks[nb * ATP + k8 + q + 4];
            }
            #pragma unroll
            for (int mt = 0; mt < 4; mt++)
                #pragma unroll
                for (int nt = 0; nt < 2; nt++) mma8(S[mt][nt], af[mt], bf[nt]);
        }

        // mask + scale -> Ps (fp32)
        const unsigned char* mp = g_mask + ((size_t)b * LQ + i0) * LQ + j0;
        #pragma unroll
        for (int mt = 0; mt < 4; mt++)
            #pragma unroll
            for (int h2 = 0; h2 < 2; h2++) {
                int row = wm * 64 + mt * 16 + g + h2 * 8;
                #pragma unroll
                for (int nt = 0; nt < 2; nt++) {
                    int col = wn * 16 + nt * 8 + 2 * q;
                    uchar2 m2 = *(const uchar2*)&mp[(size_t)(i0 ? row : row) * 0 + (size_t)(row + i0 - i0) * LQ + col]; // see below
                    (void)m2;
                    uchar2 mk = *(const uchar2*)&mp[(size_t)row * LQ + col];
                    float2 v;
                    v.x = mk.x ? -1e30f : S[mt][nt][h2 * 2 + 0] * 0.125f;
                    v.y = mk.y ? -1e30f : S[mt][nt][h2 * 2 + 1] * 0.125f;
                    *(float2*)&Ps[row * ATP + col] = v;
                }
            }
        __syncthreads();

        // online softmax, one thread per query row; write P back as tf32
        if (tid < 128) {
            float m_old = mrow[tid], mx = m_old;
            float* srp = Ps + tid * ATP;
            #pragma unroll 8
            for (int c = 0; c < 64; c++) mx = fmaxf(mx, srp[c]);
            float sc = __expf(m_old - mx);
            float sum = 0.f;
            uint32_t* pu = Pu + tid * ATP;
            #pragma unroll 8
            for (int c = 0; c < 64; c++) {
                float p = __expf(srp[c] - mx);
                sum += p;
                pu[c] = f2tf(p);
            }
            lrow[tid] = lrow[tid] * sc + sum;
            mrow[tid] = mx;
            srow[tid] = sc;
        }
        __syncthreads();

        // rescale O, then O += P V : M=128, N=64 dh, K=64 keys
        #pragma unroll
        for (int mt = 0; mt < 4; mt++) {
            int mb = wm * 64 + mt * 16;
            float s0 = srow[mb + g], s1 = srow[mb + g + 8];
            #pragma unroll
            for (int nt = 0; nt < 2; nt++) {
                O[mt][nt][0] *= s0; O[mt][nt][1] *= s0;
                O[mt][nt][2] *= s1; O[mt][nt][3] *= s1;
            }
        }
        #pragma unroll
        for (int ks = 0; ks < 8; ks++) {
            int k8 = ks * 8;
            uint32_t af[4][4], bf[2][2];
            #pragma unroll
            for (int mt = 0; mt < 4; mt++) {
                int mb = wm * 64 + mt * 16;
                af[mt][0] = Pu[(mb + g) * ATP + k8 + q];
                af[mt][1] = Pu[(mb + g + 8) * ATP + k8 + q];
                af[mt][2] = Pu[(mb + g) * ATP + k8 + q + 4];
                af[mt][3] = Pu[(mb + g + 8) * ATP + k8 + q + 4];
            }
            #pragma unroll
            for (int nt = 0; nt < 2; nt++) {
                int nb = wn * 16 + nt * 8 + g;       // dh column
                bf[nt][0] = Vs[(k8 + q) * ATP + nb];
                bf[nt][1] = Vs[(k8 + q + 4) * ATP + nb];
            }
            #pragma unroll
            for (int mt = 0; mt < 4; mt++)
                #pragma unroll
                for (int nt = 0; nt < 2; nt++) mma8(O[mt][nt], af[mt], bf[nt]);
        }
        __syncthreads();
    }

    // epilogue: out[Lq,bz,d] = O/l + h
    #pragma unroll
    for (int mt = 0; mt < 4; mt++)
        #pragma unroll
        for (int h2 = 0; h2 < 2; h2++) {
            int row = wm * 64 + mt * 16 + g + h2 * 8;
            int gi = i0 + row;
            float inv_l = 1.f / lrow[row];
            #pragma unroll
            for (int nt = 0; nt < 2; nt++) {
                int n = wn * 16 + nt * 8 + 2 * q;
                int col = head * DH + n;
                float2 hv = *(const float2*)&g_h[((size_t)b * LQ + gi) * D + col];
                float2 o;
                o.x = O[mt][nt][h2 * 2 + 0] * inv_l + hv.x;
                o.y = O[mt][nt][h2 * 2 + 1] * inv_l + hv.y;
                *(float2*)&out[((size_t)gi * BZ + b) * D + col] = o;
            }
        }
}

// ---------------- host ----------------
extern "C" void kernel_launch(void* const* d_in, const int* in_sizes, int n_in,
                              void* d_out, int out_size) {
    const float* query = (const float*)d_in[0];
    const float* seg   = (const float*)d_in[1];
    const float* Wq    = (const float*)d_in[2];
    const float* bq    = (const float*)d_in[3];
    const float* Wk    = (const float*)d_in[4];
    const float* bk    = (const float*)d_in[5];
    const float* Wv    = (const float*)d_in[6];
    const float* bv    = (const float*)d_in[7];
    float* out = (float*)d_out;

    float *hp, *qp, *kp, *vp;
    cudaGetSymbolAddress((void**)&hp, g_h);
    cudaGetSymbolAddress((void**)&qp, g_Q);
    cudaGetSymbolAddress((void**)&kp, g_K);
    cudaGetSymbolAddress((void**)&vp, g_V);

    k_transpose<<<(BZ * LQ * (D / 4) + 255) / 256, 256>>>(query);
    k_norms<<<(BZ * LQ * 32) / 256, 256>>>();

    dim3 gg(D / 128, BZ * LQ / 128);   // (4, 64)
    k_gemm<<<gg, 256>>>(hp, Wq, bq, qp, BZ * LQ, D, D);
    k_gemm<<<gg, 256>>>(hp, Wk, bk, kp, BZ * LQ, D, D);
    k_gemm<<<gg, 256>>>(hp, Wv, bv, vp, BZ * LQ, D, D);

    dim3 gm(LQ / 128, LQ / 128, BZ);   // (8, 8, 8)
    k_mask<<<gm, 256>>>(seg);

    int smem = (128 * ATP + 64 * ATP + 64 * ATP + 128 * ATP + 3 * 128) * (int)sizeof(float);
    cudaFuncSetAttribute(k_attn, cudaFuncAttributeMaxDynamicSharedMemorySize, smem);
    dim3 ga(LQ / 128, NH, BZ);         // (8, 8, 8)
    k_attn<<<ga, 256, smem>>>(out);
}

// round 5
// speedup vs baseline: 2.5211x; 1.1878x over previous
#include <cuda_runtime.h>
#include <stdint.h>
#include <math.h>

#define BZ 8
#define LQ 1024
#define D  512
#define NH 8
#define DH 64

// ---------------- scratch ----------------
__device__ float g_h[BZ * LQ * D];
__device__ float g_Q[BZ * LQ * D];
__device__ float g_K[BZ * LQ * D];
__device__ float g_V[BZ * LQ * D];
__device__ float g_norm[BZ * LQ];
__device__ unsigned char g_mask[(size_t)BZ * LQ * LQ];  // 1 = masked

// ---------------- tf32 helpers ----------------
__device__ __forceinline__ uint32_t f2tf(float f) {
    uint32_t u;
    asm("cvt.rna.tf32.f32 %0, %1;" : "=r"(u) : "f"(f));
    return u;
}
__device__ __forceinline__ void mma8(float* d, const uint32_t* a, const uint32_t* b) {
    asm volatile(
        "mma.sync.aligned.m16n8k8.row.col.f32.tf32.tf32.f32 "
        "{%0,%1,%2,%3},{%4,%5,%6,%7},{%8,%9},{%0,%1,%2,%3};\n"
        : "+f"(d[0]), "+f"(d[1]), "+f"(d[2]), "+f"(d[3])
        : "r"(a[0]), "r"(a[1]), "r"(a[2]), "r"(a[3]), "r"(b[0]), "r"(b[1]));
}

// ---------------- K1: transpose query[Lq,bz,d] -> h[bz,Lq,d] + row norms ----------------
// One block per source row (128 threads, 1 float4 each).
__global__ __launch_bounds__(128) void k_prep(const float* __restrict__ q) {
    int row = blockIdx.x;              // r = i*BZ + b
    int i = row >> 3, b = row & 7;
    int tid = threadIdx.x, lane = tid & 31, wid = tid >> 5;
    float4 v = ((const float4*)(q + (size_t)row * D))[tid];
    ((float4*)g_h)[(size_t)(b * LQ + i) * (D / 4) + tid] = v;
    float s = v.x * v.x + v.y * v.y + v.z * v.z + v.w * v.w;
    #pragma unroll
    for (int o = 16; o; o >>= 1) s += __shfl_xor_sync(0xffffffffu, s, o);
    __shared__ float ws[4];
    if (lane == 0) ws[wid] = s;
    __syncthreads();
    if (tid == 0)
        g_norm[b * LQ + i] = fmaxf(sqrtf(ws[0] + ws[1] + ws[2] + ws[3]), 1e-8f);
}

// ---------------- K2: fused QKV tf32 GEMM  C_z = h @ W_z^T + b_z ----------------
// 128x128 tile, 8 warps (2x4), warp tile 64x32, k-panel 16, double buffered.
#define KP 20
__global__ __launch_bounds__(256) void k_gemm_qkv(
    const float* __restrict__ A,
    const float* __restrict__ W0, const float* __restrict__ W1, const float* __restrict__ W2,
    const float* __restrict__ b0, const float* __restrict__ b1, const float* __restrict__ b2,
    float* __restrict__ C0, float* __restrict__ C1, float* __restrict__ C2)
{
    const int M = BZ * LQ, N = D, K = D;
    const float* B    = (blockIdx.z == 0) ? W0 : (blockIdx.z == 1) ? W1 : W2;
    const float* bias = (blockIdx.z == 0) ? b0 : (blockIdx.z == 1) ? b1 : b2;
    float*       C    = (blockIdx.z == 0) ? C0 : (blockIdx.z == 1) ? C1 : C2;

    __shared__ uint32_t As[2][128][KP];
    __shared__ uint32_t Bs[2][128][KP];
    int tid = threadIdx.x, lane = tid & 31, wid = tid >> 5;
    int g = lane >> 2, q = lane & 3;
    int wm = wid >> 2, wn = wid & 3;
    int m0 = blockIdx.y * 128, n0 = blockIdx.x * 128;

    int lrow = tid >> 1, lc = (tid & 1) * 8;
    const float* Ap = A + (size_t)(m0 + lrow) * K + lc;
    const float* Bp = B + (size_t)(n0 + lrow) * K + lc;

    float4 a0r = *(const float4*)Ap, a1r = *(const float4*)(Ap + 4);
    float4 b0r = *(const float4*)Bp, b1r = *(const float4*)(Bp + 4);
    {
        uint32_t* d = &As[0][lrow][lc];
        d[0]=f2tf(a0r.x); d[1]=f2tf(a0r.y); d[2]=f2tf(a0r.z); d[3]=f2tf(a0r.w);
        d[4]=f2tf(a1r.x); d[5]=f2tf(a1r.y); d[6]=f2tf(a1r.z); d[7]=f2tf(a1r.w);
        uint32_t* e = &Bs[0][lrow][lc];
        e[0]=f2tf(b0r.x); e[1]=f2tf(b0r.y); e[2]=f2tf(b0r.z); e[3]=f2tf(b0r.w);
        e[4]=f2tf(b1r.x); e[5]=f2tf(b1r.y); e[6]=f2tf(b1r.z); e[7]=f2tf(b1r.w);
    }
    __syncthreads();

    float acc[4][4][4] = {};
    int nP = K / 16, buf = 0;
    for (int p = 0; p < nP; p++) {
        if (p + 1 < nP) {
            const float* Ap2 = Ap + (p + 1) * 16;
            const float* Bp2 = Bp + (p + 1) * 16;
            a0r = *(const float4*)Ap2; a1r = *(const float4*)(Ap2 + 4);
            b0r = *(const float4*)Bp2; b1r = *(const float4*)(Bp2 + 4);
        }
        #pragma unroll
        for (int ks = 0; ks < 2; ks++) {
            int k8 = ks * 8;
            uint32_t af[4][4], bf[4][2];
            #pragma unroll
            for (int mt = 0; mt < 4; mt++) {
                int mb = wm * 64 + mt * 16;
                af[mt][0] = As[buf][mb + g][k8 + q];
                af[mt][1] = As[buf][mb + g + 8][k8 + q];
                af[mt][2] = As[buf][mb + g][k8 + q + 4];
                af[mt][3] = As[buf][mb + g + 8][k8 + q + 4];
            }
            #pragma unroll
            for (int nt = 0; nt < 4; nt++) {
                int nb = wn * 32 + nt * 8 + g;
                bf[nt][0] = Bs[buf][nb][k8 + q];
                bf[nt][1] = Bs[buf][nb][k8 + q + 4];
            }
            #pragma unroll
            for (int mt = 0; mt < 4; mt++)
                #pragma unroll
                for (int nt = 0; nt < 4; nt++) mma8(acc[mt][nt], af[mt], bf[nt]);
        }
        if (p + 1 < nP) {
            int nb = buf ^ 1;
            uint32_t* d = &As[nb][lrow][lc];
            d[0]=f2tf(a0r.x); d[1]=f2tf(a0r.y); d[2]=f2tf(a0r.z); d[3]=f2tf(a0r.w);
            d[4]=f2tf(a1r.x); d[5]=f2tf(a1r.y); d[6]=f2tf(a1r.z); d[7]=f2tf(a1r.w);
            uint32_t* e = &Bs[nb][lrow][lc];
            e[0]=f2tf(b0r.x); e[1]=f2tf(b0r.y); e[2]=f2tf(b0r.z); e[3]=f2tf(b0r.w);
            e[4]=f2tf(b1r.x); e[5]=f2tf(b1r.y); e[6]=f2tf(b1r.z); e[7]=f2tf(b1r.w);
            buf = nb;
        }
        __syncthreads();
    }

    #pragma unroll
    for (int mt = 0; mt < 4; mt++)
        #pragma unroll
        for (int h2 = 0; h2 < 2; h2++) {
            int m = m0 + wm * 64 + mt * 16 + g + h2 * 8;
            #pragma unroll
            for (int nt = 0; nt < 4; nt++) {
                int n = n0 + wn * 32 + nt * 8 + 2 * q;
                float2 v;
                v.x = acc[mt][nt][h2 * 2 + 0] + bias[n];
                v.y = acc[mt][nt][h2 * 2 + 1] + bias[n + 1];
                *(float2*)&C[(size_t)m * N + n] = v;
            }
        }
}

// ---------------- K3: mask via single tf32 Gram + fp32 fixup near threshold ----------------
__global__ __launch_bounds__(256) void k_mask(const float* __restrict__ seg) {
    __shared__ uint32_t As[2][128][KP];
    __shared__ uint32_t Bs[2][128][KP];
    __shared__ float si[128], ei[128], li[128], ni[128];
    __shared__ float sj[128], ej[128], lj[128], nj[128];
    int b = blockIdx.z;
    int i0 = blockIdx.y * 128, j0 = blockIdx.x * 128;
    int tid = threadIdx.x, lane = tid & 31, wid = tid >> 5;
    int g = lane >> 2, q = lane & 3;
    int wm = wid >> 2, wn = wid & 3;

    if (tid < 128) {
        int gi = b * LQ + i0 + tid;
        float c = seg[gi * 2], l = seg[gi * 2 + 1];
        si[tid] = c - 0.5f * l; ei[tid] = c + 0.5f * l; li[tid] = l;
        ni[tid] = g_norm[gi];
    } else {
        int t = tid - 128;
        int gj = b * LQ + j0 + t;
        float c = seg[gj * 2], l = seg[gj * 2 + 1];
        sj[t] = c - 0.5f * l; ej[t] = c + 0.5f * l; lj[t] = l;
        nj[t] = g_norm[gj];
    }

    const float* Abase = g_h + (size_t)b * LQ * D;
    int lrow = tid >> 1, lc = (tid & 1) * 8;
    const float* Ap = Abase + (size_t)(i0 + lrow) * D + lc;
    const float* Bp = Abase + (size_t)(j0 + lrow) * D + lc;

    float4 a0r = *(const float4*)Ap, a1r = *(const float4*)(Ap + 4);
    float4 b0r = *(const float4*)Bp, b1r = *(const float4*)(Bp + 4);
    {
        uint32_t* d = &As[0][lrow][lc];
        d[0]=f2tf(a0r.x); d[1]=f2tf(a0r.y); d[2]=f2tf(a0r.z); d[3]=f2tf(a0r.w);
        d[4]=f2tf(a1r.x); d[5]=f2tf(a1r.y); d[6]=f2tf(a1r.z); d[7]=f2tf(a1r.w);
        uint32_t* e = &Bs[0][lrow][lc];
        e[0]=f2tf(b0r.x); e[1]=f2tf(b0r.y); e[2]=f2tf(b0r.z); e[3]=f2tf(b0r.w);
        e[4]=f2tf(b1r.x); e[5]=f2tf(b1r.y); e[6]=f2tf(b1r.z); e[7]=f2tf(b1r.w);
    }
    __syncthreads();

    float acc[4][4][4] = {};
    int nP = D / 16, buf = 0;
    for (int p = 0; p < nP; p++) {
        if (p + 1 < nP) {
            const float* Ap2 = Ap + (p + 1) * 16;
            const float* Bp2 = Bp + (p + 1) * 16;
            a0r = *(const float4*)Ap2; a1r = *(const float4*)(Ap2 + 4);
            b0r = *(const float4*)Bp2; b1r = *(const float4*)(Bp2 + 4);
        }
        #pragma unroll
        for (int ks = 0; ks < 2; ks++) {
            int k8 = ks * 8;
            uint32_t af[4][4], bf[4][2];
            #pragma unroll
            for (int mt = 0; mt < 4; mt++) {
                int mb = wm * 64 + mt * 16;
                af[mt][0] = As[buf][mb + g][k8 + q];
                af[mt][1] = As[buf][mb + g + 8][k8 + q];
                af[mt][2] = As[buf][mb + g][k8 + q + 4];
                af[mt][3] = As[buf][mb + g + 8][k8 + q + 4];
            }
            #pragma unroll
            for (int nt = 0; nt < 4; nt++) {
                int nb = wn * 32 + nt * 8 + g;
                bf[nt][0] = Bs[buf][nb][k8 + q];
                bf[nt][1] = Bs[buf][nb][k8 + q + 4];
            }
            #pragma unroll
            for (int mt = 0; mt < 4; mt++)
                #pragma unroll
                for (int nt = 0; nt < 4; nt++) mma8(acc[mt][nt], af[mt], bf[nt]);
        }
        if (p + 1 < nP) {
            int nb = buf ^ 1;
            uint32_t* d = &As[nb][lrow][lc];
            d[0]=f2tf(a0r.x); d[1]=f2tf(a0r.y); d[2]=f2tf(a0r.z); d[3]=f2tf(a0r.w);
            d[4]=f2tf(a1r.x); d[5]=f2tf(a1r.y); d[6]=f2tf(a1r.z); d[7]=f2tf(a1r.w);
            uint32_t* e = &Bs[nb][lrow][lc];
            e[0]=f2tf(b0r.x); e[1]=f2tf(b0r.y); e[2]=f2tf(b0r.z); e[3]=f2tf(b0r.w);
            e[4]=f2tf(b1r.x); e[5]=f2tf(b1r.y); e[6]=f2tf(b1r.z); e[7]=f2tf(b1r.w);
            buf = nb;
        }
        __syncthreads();
    }

    #pragma unroll
    for (int mt = 0; mt < 4; mt++)
        #pragma unroll
        for (int h2 = 0; h2 < 2; h2++) {
            int ii = wm * 64 + mt * 16 + g + h2 * 8;
            int gi = i0 + ii;                       // row within batch
            unsigned char* mp = g_mask + ((size_t)b * LQ + gi) * LQ + j0;
            #pragma unroll
            for (int nt = 0; nt < 4; nt++) {
                int jc = wn * 32 + nt * 8 + 2 * q;
                uchar2 r;
                #pragma unroll
                for (int e = 0; e < 2; e++) {
                    int jj = jc + e, gj = j0 + jj;
                    float inv_nn = 1.f / (ni[ii] * nj[jj]);
                    float cosv = acc[mt][nt][h2 * 2 + e] * inv_nn;
                    if (fabsf(cosv - 0.2f) < 2e-3f) {
                        // exact fp32 recompute for borderline pairs (rare)
                        const float4* ra = (const float4*)(Abase + (size_t)gi * D);
                        const float4* rb = (const float4*)(Abase + (size_t)gj * D);
                        float dot = 0.f;
                        #pragma unroll 4
                        for (int k = 0; k < D / 4; k++) {
                            float4 x = ra[k], y = rb[k];
                            dot += x.x * y.x + x.y * y.y + x.z * y.z + x.w * y.w;
                        }
                        cosv = dot * inv_nn;
                    }
                    float inter = fmaxf(fminf(ei[ii], ej[jj]) - fmaxf(si[ii], sj[jj]), 0.f);
                    float uni   = li[ii] + lj[jj] - inter;
                    float iou   = inter / uni;
                    bool masked = (cosv <= 0.2f) || (iou > 0.2f && gi != gj);
                    if (e == 0) r.x = masked ? 1 : 0; else r.y = masked ? 1 : 0;
                }
                *(uchar2*)&mp[jc] = r;
            }
        }
}

// ---------------- K4: tensor-core flash attention (parallel warp softmax) ----------------
#define ATP 68
__global__ __launch_bounds__(256) void k_attn(float* __restrict__ out) {
    extern __shared__ float sm[];
    uint32_t* Qs = (uint32_t*)sm;                 // 128*68 (pre-scaled by 1/8)
    uint32_t* Ks = Qs + 128 * ATP;                // 64*68
    uint32_t* Vs = Ks + 64 * ATP;                 // 64*68
    float*    Ps = (float*)(Vs + 64 * ATP);       // 128*68
    uint32_t* Pu = (uint32_t*)Ps;
    float* mrow = Ps + 128 * ATP;
    float* lrow = mrow + 128;
    float* srow = lrow + 128;

    int i0 = blockIdx.x * 128, head = blockIdx.y, b = blockIdx.z;
    int tid = threadIdx.x, lane = tid & 31, wid = tid >> 5;
    int g = lane >> 2, q = lane & 3;
    int wm = wid >> 2, wn = wid & 3;
    const size_t base = (size_t)b * LQ * D + head * DH;

    // load Q tile (x 1/8, tf32)
    #pragma unroll
    for (int s = 0; s < 8; s++) {
        int f = tid + s * 256;
        int r = f >> 4, c4 = (f & 15) << 2;
        float4 v = *(const float4*)&g_Q[base + (size_t)(i0 + r) * D + c4];
        uint32_t* d = &Qs[r * ATP + c4];
        d[0] = f2tf(v.x * 0.125f); d[1] = f2tf(v.y * 0.125f);
        d[2] = f2tf(v.z * 0.125f); d[3] = f2tf(v.w * 0.125f);
    }
    if (tid < 128) { mrow[tid] = -1e30f; lrow[tid] = 0.f; }
    float O[4][2][4] = {};
    __syncthreads();

    for (int j0 = 0; j0 < LQ; j0 += 64) {
        #pragma unroll
        for (int s = 0; s < 4; s++) {
            int f = tid + s * 256;
            int r = f >> 4, c4 = (f & 15) << 2;
            size_t ga = base + (size_t)(j0 + r) * D + c4;
            float4 kv = *(const float4*)&g_K[ga];
            uint32_t* d = &Ks[r * ATP + c4];
            d[0] = f2tf(kv.x); d[1] = f2tf(kv.y); d[2] = f2tf(kv.z); d[3] = f2tf(kv.w);
            float4 vv = *(const float4*)&g_V[ga];
            uint32_t* e = &Vs[r * ATP + c4];
            e[0] = f2tf(vv.x); e[1] = f2tf(vv.y); e[2] = f2tf(vv.z); e[3] = f2tf(vv.w);
        }
        __syncthreads();

        // S = (Q/8) K^T
        float S[4][2][4] = {};
        #pragma unroll
        for (int ks = 0; ks < 8; ks++) {
            int k8 = ks * 8;
            uint32_t af[4][4], bf[2][2];
            #pragma unroll
            for (int mt = 0; mt < 4; mt++) {
                int mb = wm * 64 + mt * 16;
                af[mt][0] = Qs[(mb + g) * ATP + k8 + q];
                af[mt][1] = Qs[(mb + g + 8) * ATP + k8 + q];
                af[mt][2] = Qs[(mb + g) * ATP + k8 + q + 4];
                af[mt][3] = Qs[(mb + g + 8) * ATP + k8 + q + 4];
            }
            #pragma unroll
            for (int nt = 0; nt < 2; nt++) {
                int nb = wn * 16 + nt * 8 + g;
                bf[nt][0] = Ks[nb * ATP + k8 + q];
                bf[nt][1] = Ks[nb * ATP + k8 + q + 4];
            }
            #pragma unroll
            for (int mt = 0; mt < 4; mt++)
                #pragma unroll
                for (int nt = 0; nt < 2; nt++) mma8(S[mt][nt], af[mt], bf[nt]);
        }

        // mask -> Ps (fp32)
        const unsigned char* mp = g_mask + ((size_t)b * LQ + i0) * LQ + j0;
        #pragma unroll
        for (int mt = 0; mt < 4; mt++)
            #pragma unroll
            for (int h2 = 0; h2 < 2; h2++) {
                int row = wm * 64 + mt * 16 + g + h2 * 8;
                #pragma unroll
                for (int nt = 0; nt < 2; nt++) {
                    int col = wn * 16 + nt * 8 + 2 * q;
                    uchar2 mk = *(const uchar2*)&mp[(size_t)row * LQ + col];
                    float2 v;
                    v.x = mk.x ? -1e30f : S[mt][nt][h2 * 2 + 0];
                    v.y = mk.y ? -1e30f : S[mt][nt][h2 * 2 + 1];
                    *(float2*)&Ps[row * ATP + col] = v;
                }
            }
        __syncthreads();

        // parallel online softmax: warp w owns rows [w*16, w*16+16); 32 lanes x 2 cols
        #pragma unroll
        for (int rr = 0; rr < 16; rr++) {
            int r = wid * 16 + rr;
            float2 v = *(float2*)&Ps[r * ATP + lane * 2];
            float mx = fmaxf(v.x, v.y);
            #pragma unroll
            for (int o = 16; o; o >>= 1) mx = fmaxf(mx, __shfl_xor_sync(0xffffffffu, mx, o));
            float m_old = mrow[r];
            float mnew = fmaxf(m_old, mx);
            float p0 = __expf(v.x - mnew), p1 = __expf(v.y - mnew);
            float s = p0 + p1;
            #pragma unroll
            for (int o = 16; o; o >>= 1) s += __shfl_xor_sync(0xffffffffu, s, o);
            uint32_t* pu = Pu + r * ATP + lane * 2;
            pu[0] = f2tf(p0); pu[1] = f2tf(p1);
            if (lane == 0) {
                float sc = __expf(m_old - mnew);
                lrow[r] = lrow[r] * sc + s;
                mrow[r] = mnew;
                srow[r] = sc;
            }
        }
        __syncthreads();

        // rescale O; O += P V
        #pragma unroll
        for (int mt = 0; mt < 4; mt++) {
            int mb = wm * 64 + mt * 16;
            float s0 = srow[mb + g], s1 = srow[mb + g + 8];
            #pragma unroll
            for (int nt = 0; nt < 2; nt++) {
                O[mt][nt][0] *= s0; O[mt][nt][1] *= s0;
                O[mt][nt][2] *= s1; O[mt][nt][3] *= s1;
            }
        }
        #pragma unroll
        for (int ks = 0; ks < 8; ks++) {
            int k8 = ks * 8;
            uint32_t af[4][4], bf[2][2];
            #pragma unroll
            for (int mt = 0; mt < 4; mt++) {
                int mb = wm * 64 + mt * 16;
                af[mt][0] = Pu[(mb + g) * ATP + k8 + q];
                af[mt][1] = Pu[(mb + g + 8) * ATP + k8 + q];
                af[mt][2] = Pu[(mb + g) * ATP + k8 + q + 4];
                af[mt][3] = Pu[(mb + g + 8) * ATP + k8 + q + 4];
            }
            #pragma unroll
            for (int nt = 0; nt < 2; nt++) {
                int nb = wn * 16 + nt * 8 + g;
                bf[nt][0] = Vs[(k8 + q) * ATP + nb];
                bf[nt][1] = Vs[(k8 + q + 4) * ATP + nb];
            }
            #pragma unroll
            for (int mt = 0; mt < 4; mt++)
                #pragma unroll
                for (int nt = 0; nt < 2; nt++) mma8(O[mt][nt], af[mt], bf[nt]);
        }
        __syncthreads();
    }

    // epilogue
    #pragma unroll
    for (int mt = 0; mt < 4; mt++)
        #pragma unroll
        for (int h2 = 0; h2 < 2; h2++) {
            int row = wm * 64 + mt * 16 + g + h2 * 8;
            int gi = i0 + row;
            float inv_l = 1.f / lrow[row];
            #pragma unroll
            for (int nt = 0; nt < 2; nt++) {
                int n = wn * 16 + nt * 8 + 2 * q;
                int col = head * DH + n;
                float2 hv = *(const float2*)&g_h[((size_t)b * LQ + gi) * D + col];
                float2 o;
                o.x = O[mt][nt][h2 * 2 + 0] * inv_l + hv.x;
                o.y = O[mt][nt][h2 * 2 + 1] * inv_l + hv.y;
                *(float2*)&out[((size_t)gi * BZ + b) * D + col] = o;
            }
        }
}

// ---------------- host ----------------
extern "C" void kernel_launch(void* const* d_in, const int* in_sizes, int n_in,
                              void* d_out, int out_size) {
    const float* query = (const float*)d_in[0];
    const float* seg   = (const float*)d_in[1];
    const float* Wq    = (const float*)d_in[2];
    const float* bq    = (const float*)d_in[3];
    const float* Wk    = (const float*)d_in[4];
    const float* bk    = (const float*)d_in[5];
    const float* Wv    = (const float*)d_in[6];
    const float* bv    = (const float*)d_in[7];
    float* out = (float*)d_out;

    float *hp, *qp, *kp, *vp;
    cudaGetSymbolAddress((void**)&hp, g_h);
    cudaGetSymbolAddress((void**)&qp, g_Q);
    cudaGetSymbolAddress((void**)&kp, g_K);
    cudaGetSymbolAddress((void**)&vp, g_V);

    k_prep<<<BZ * LQ, 128>>>(query);

    dim3 gg(D / 128, BZ * LQ / 128, 3);   // (4, 64, 3)
    k_gemm_qkv<<<gg, 256>>>(hp, Wq, Wk, Wv, bq, bk, bv, qp, kp, vp);

    dim3 gm(LQ / 128, LQ / 128, BZ);      // (8, 8, 8)
    k_mask<<<gm, 256>>>(seg);

    int smem = (128 * ATP + 64 * ATP + 64 * ATP + 128 * ATP + 3 * 128) * (int)sizeof(float);
    cudaFuncSetAttribute(k_attn, cudaFuncAttributeMaxDynamicSharedMemorySize, smem);
    dim3 ga(LQ / 128, NH, BZ);            // (8, 8, 8)
    k_attn<<<ga, 256, smem>>>(out);
}

// round 6
// speedup vs baseline: 3.3031x; 1.3102x over previous
#include <cuda_runtime.h>
#include <stdint.h>
#include <math.h>

#define BZ 8
#define LQ 1024
#define D  512
#define NH 8
#define DH 64

// ---------------- scratch ----------------
__device__ float g_h[BZ * LQ * D];
__device__ float g_Q[BZ * LQ * D];   // tf32 bits, pre-scaled by 1/8
__device__ float g_K[BZ * LQ * D];   // tf32 bits
__device__ float g_V[BZ * LQ * D];   // tf32 bits
__device__ float g_norm[BZ * LQ];
__device__ unsigned char g_mask[(size_t)BZ * LQ * LQ];  // 1 = masked

// ---------------- helpers ----------------
__device__ __forceinline__ uint32_t f2tf(float f) {
    uint32_t u;
    asm("cvt.rna.tf32.f32 %0, %1;" : "=r"(u) : "f"(f));
    return u;
}
__device__ __forceinline__ void mma8(float* d, const uint32_t* a, const uint32_t* b) {
    asm volatile(
        "mma.sync.aligned.m16n8k8.row.col.f32.tf32.tf32.f32 "
        "{%0,%1,%2,%3},{%4,%5,%6,%7},{%8,%9},{%0,%1,%2,%3};\n"
        : "+f"(d[0]), "+f"(d[1]), "+f"(d[2]), "+f"(d[3])
        : "r"(a[0]), "r"(a[1]), "r"(a[2]), "r"(a[3]), "r"(b[0]), "r"(b[1]));
}
__device__ __forceinline__ void cpasync16(uint32_t saddr, const void* g) {
    asm volatile("cp.async.cg.shared.global [%0], [%1], 16;" :: "r"(saddr), "l"(g));
}
#define CP_COMMIT() asm volatile("cp.async.commit_group;")
#define CP_WAIT0()  asm volatile("cp.async.wait_group 0;")

// ---------------- K1: transpose + row norms ----------------
__global__ __launch_bounds__(128) void k_prep(const float* __restrict__ q) {
    int row = blockIdx.x;              // r = i*BZ + b
    int i = row >> 3, b = row & 7;
    int tid = threadIdx.x, lane = tid & 31, wid = tid >> 5;
    float4 v = ((const float4*)(q + (size_t)row * D))[tid];
    ((float4*)g_h)[(size_t)(b * LQ + i) * (D / 4) + tid] = v;
    float s = v.x * v.x + v.y * v.y + v.z * v.z + v.w * v.w;
    #pragma unroll
    for (int o = 16; o; o >>= 1) s += __shfl_xor_sync(0xffffffffu, s, o);
    __shared__ float ws[4];
    if (lane == 0) ws[wid] = s;
    __syncthreads();
    if (tid == 0)
        g_norm[b * LQ + i] = fmaxf(sqrtf(ws[0] + ws[1] + ws[2] + ws[3]), 1e-8f);
}

// ---------------- K2: fused QKV tf32 GEMM, epilogue stores tf32 bits ----------------
#define KP 20
__global__ __launch_bounds__(256) void k_gemm_qkv(
    const float* __restrict__ A,
    const float* __restrict__ W0, const float* __restrict__ W1, const float* __restrict__ W2,
    const float* __restrict__ b0, const float* __restrict__ b1, const float* __restrict__ b2,
    float* __restrict__ C0, float* __restrict__ C1, float* __restrict__ C2)
{
    const int N = D, K = D;
    int z = blockIdx.z;
    const float* B    = (z == 0) ? W0 : (z == 1) ? W1 : W2;
    const float* bias = (z == 0) ? b0 : (z == 1) ? b1 : b2;
    float*       C    = (z == 0) ? C0 : (z == 1) ? C1 : C2;
    float oscale = (z == 0) ? 0.125f : 1.0f;

    __shared__ uint32_t As[2][128][KP];
    __shared__ uint32_t Bs[2][128][KP];
    int tid = threadIdx.x, lane = tid & 31, wid = tid >> 5;
    int g = lane >> 2, q = lane & 3;
    int wm = wid >> 2, wn = wid & 3;
    int m0 = blockIdx.y * 128, n0 = blockIdx.x * 128;

    int lrow = tid >> 1, lc = (tid & 1) * 8;
    const float* Ap = A + (size_t)(m0 + lrow) * K + lc;
    const float* Bp = B + (size_t)(n0 + lrow) * K + lc;

    float4 a0r = *(const float4*)Ap, a1r = *(const float4*)(Ap + 4);
    float4 b0r = *(const float4*)Bp, b1r = *(const float4*)(Bp + 4);
    {
        uint32_t* d = &As[0][lrow][lc];
        d[0]=f2tf(a0r.x); d[1]=f2tf(a0r.y); d[2]=f2tf(a0r.z); d[3]=f2tf(a0r.w);
        d[4]=f2tf(a1r.x); d[5]=f2tf(a1r.y); d[6]=f2tf(a1r.z); d[7]=f2tf(a1r.w);
        uint32_t* e = &Bs[0][lrow][lc];
        e[0]=f2tf(b0r.x); e[1]=f2tf(b0r.y); e[2]=f2tf(b0r.z); e[3]=f2tf(b0r.w);
        e[4]=f2tf(b1r.x); e[5]=f2tf(b1r.y); e[6]=f2tf(b1r.z); e[7]=f2tf(b1r.w);
    }
    __syncthreads();

    float acc[4][4][4] = {};
    int nP = K / 16, buf = 0;
    for (int p = 0; p < nP; p++) {
        if (p + 1 < nP) {
            const float* Ap2 = Ap + (p + 1) * 16;
            const float* Bp2 = Bp + (p + 1) * 16;
            a0r = *(const float4*)Ap2; a1r = *(const float4*)(Ap2 + 4);
            b0r = *(const float4*)Bp2; b1r = *(const float4*)(Bp2 + 4);
        }
        #pragma unroll
        for (int ks = 0; ks < 2; ks++) {
            int k8 = ks * 8;
            uint32_t af[4][4], bf[4][2];
            #pragma unroll
            for (int mt = 0; mt < 4; mt++) {
                int mb = wm * 64 + mt * 16;
                af[mt][0] = As[buf][mb + g][k8 + q];
                af[mt][1] = As[buf][mb + g + 8][k8 + q];
                af[mt][2] = As[buf][mb + g][k8 + q + 4];
                af[mt][3] = As[buf][mb + g + 8][k8 + q + 4];
            }
            #pragma unroll
            for (int nt = 0; nt < 4; nt++) {
                int nb = wn * 32 + nt * 8 + g;
                bf[nt][0] = Bs[buf][nb][k8 + q];
                bf[nt][1] = Bs[buf][nb][k8 + q + 4];
            }
            #pragma unroll
            for (int mt = 0; mt < 4; mt++)
                #pragma unroll
                for (int nt = 0; nt < 4; nt++) mma8(acc[mt][nt], af[mt], bf[nt]);
        }
        if (p + 1 < nP) {
            int nb = buf ^ 1;
            uint32_t* d = &As[nb][lrow][lc];
            d[0]=f2tf(a0r.x); d[1]=f2tf(a0r.y); d[2]=f2tf(a0r.z); d[3]=f2tf(a0r.w);
            d[4]=f2tf(a1r.x); d[5]=f2tf(a1r.y); d[6]=f2tf(a1r.z); d[7]=f2tf(a1r.w);
            uint32_t* e = &Bs[nb][lrow][lc];
            e[0]=f2tf(b0r.x); e[1]=f2tf(b0r.y); e[2]=f2tf(b0r.z); e[3]=f2tf(b0r.w);
            e[4]=f2tf(b1r.x); e[5]=f2tf(b1r.y); e[6]=f2tf(b1r.z); e[7]=f2tf(b1r.w);
            buf = nb;
        }
        __syncthreads();
    }

    // epilogue: C = tf32( (acc + bias) * oscale )
    #pragma unroll
    for (int mt = 0; mt < 4; mt++)
        #pragma unroll
        for (int h2 = 0; h2 < 2; h2++) {
            int m = m0 + wm * 64 + mt * 16 + g + h2 * 8;
            #pragma unroll
            for (int nt = 0; nt < 4; nt++) {
                int n = n0 + wn * 32 + nt * 8 + 2 * q;
                float2 v;
                v.x = __uint_as_float(f2tf((acc[mt][nt][h2 * 2 + 0] + bias[n]) * oscale));
                v.y = __uint_as_float(f2tf((acc[mt][nt][h2 * 2 + 1] + bias[n + 1]) * oscale));
                *(float2*)&C[(size_t)m * N + n] = v;
            }
        }
}

// ---------------- K3: mask via single tf32 Gram + fp32 fixup near threshold ----------------
__global__ __launch_bounds__(256) void k_mask(const float* __restrict__ seg) {
    __shared__ uint32_t As[2][128][KP];
    __shared__ uint32_t Bs[2][128][KP];
    __shared__ float si[128], ei[128], li[128], ni[128];
    __shared__ float sj[128], ej[128], lj[128], nj[128];
    int b = blockIdx.z;
    int i0 = blockIdx.y * 128, j0 = blockIdx.x * 128;
    int tid = threadIdx.x, lane = tid & 31, wid = tid >> 5;
    int g = lane >> 2, q = lane & 3;
    int wm = wid >> 2, wn = wid & 3;

    if (tid < 128) {
        int gi = b * LQ + i0 + tid;
        float c = seg[gi * 2], l = seg[gi * 2 + 1];
        si[tid] = c - 0.5f * l; ei[tid] = c + 0.5f * l; li[tid] = l;
        ni[tid] = g_norm[gi];
    } else {
        int t = tid - 128;
        int gj = b * LQ + j0 + t;
        float c = seg[gj * 2], l = seg[gj * 2 + 1];
        sj[t] = c - 0.5f * l; ej[t] = c + 0.5f * l; lj[t] = l;
        nj[t] = g_norm[gj];
    }

    const float* Abase = g_h + (size_t)b * LQ * D;
    int lrow = tid >> 1, lc = (tid & 1) * 8;
    const float* Ap = Abase + (size_t)(i0 + lrow) * D + lc;
    const float* Bp = Abase + (size_t)(j0 + lrow) * D + lc;

    float4 a0r = *(const float4*)Ap, a1r = *(const float4*)(Ap + 4);
    float4 b0r = *(const float4*)Bp, b1r = *(const float4*)(Bp + 4);
    {
        uint32_t* d = &As[0][lrow][lc];
        d[0]=f2tf(a0r.x); d[1]=f2tf(a0r.y); d[2]=f2tf(a0r.z); d[3]=f2tf(a0r.w);
        d[4]=f2tf(a1r.x); d[5]=f2tf(a1r.y); d[6]=f2tf(a1r.z); d[7]=f2tf(a1r.w);
        uint32_t* e = &Bs[0][lrow][lc];
        e[0]=f2tf(b0r.x); e[1]=f2tf(b0r.y); e[2]=f2tf(b0r.z); e[3]=f2tf(b0r.w);
        e[4]=f2tf(b1r.x); e[5]=f2tf(b1r.y); e[6]=f2tf(b1r.z); e[7]=f2tf(b1r.w);
    }
    __syncthreads();

    float acc[4][4][4] = {};
    int nP = D / 16, buf = 0;
    for (int p = 0; p < nP; p++) {
        if (p + 1 < nP) {
            const float* Ap2 = Ap + (p + 1) * 16;
            const float* Bp2 = Bp + (p + 1) * 16;
            a0r = *(const float4*)Ap2; a1r = *(const float4*)(Ap2 + 4);
            b0r = *(const float4*)Bp2; b1r = *(const float4*)(Bp2 + 4);
        }
        #pragma unroll
        for (int ks = 0; ks < 2; ks++) {
            int k8 = ks * 8;
            uint32_t af[4][4], bf[4][2];
            #pragma unroll
            for (int mt = 0; mt < 4; mt++) {
                int mb = wm * 64 + mt * 16;
                af[mt][0] = As[buf][mb + g][k8 + q];
                af[mt][1] = As[buf][mb + g + 8][k8 + q];
                af[mt][2] = As[buf][mb + g][k8 + q + 4];
                af[mt][3] = As[buf][mb + g + 8][k8 + q + 4];
            }
            #pragma unroll
            for (int nt = 0; nt < 4; nt++) {
                int nb = wn * 32 + nt * 8 + g;
                bf[nt][0] = Bs[buf][nb][k8 + q];
                bf[nt][1] = Bs[buf][nb][k8 + q + 4];
            }
            #pragma unroll
            for (int mt = 0; mt < 4; mt++)
                #pragma unroll
                for (int nt = 0; nt < 4; nt++) mma8(acc[mt][nt], af[mt], bf[nt]);
        }
        if (p + 1 < nP) {
            int nb = buf ^ 1;
            uint32_t* d = &As[nb][lrow][lc];
            d[0]=f2tf(a0r.x); d[1]=f2tf(a0r.y); d[2]=f2tf(a0r.z); d[3]=f2tf(a0r.w);
            d[4]=f2tf(a1r.x); d[5]=f2tf(a1r.y); d[6]=f2tf(a1r.z); d[7]=f2tf(a1r.w);
            uint32_t* e = &Bs[nb][lrow][lc];
            e[0]=f2tf(b0r.x); e[1]=f2tf(b0r.y); e[2]=f2tf(b0r.z); e[3]=f2tf(b0r.w);
            e[4]=f2tf(b1r.x); e[5]=f2tf(b1r.y); e[6]=f2tf(b1r.z); e[7]=f2tf(b1r.w);
            buf = nb;
        }
        __syncthreads();
    }

    #pragma unroll
    for (int mt = 0; mt < 4; mt++)
        #pragma unroll
        for (int h2 = 0; h2 < 2; h2++) {
            int ii = wm * 64 + mt * 16 + g + h2 * 8;
            int gi = i0 + ii;
            unsigned char* mp = g_mask + ((size_t)b * LQ + gi) * LQ + j0;
            #pragma unroll
            for (int nt = 0; nt < 4; nt++) {
                int jc = wn * 32 + nt * 8 + 2 * q;
                uchar2 r;
                #pragma unroll
                for (int e = 0; e < 2; e++) {
                    int jj = jc + e, gj = j0 + jj;
                    float inv_nn = 1.f / (ni[ii] * nj[jj]);
                    float cosv = acc[mt][nt][h2 * 2 + e] * inv_nn;
                    if (fabsf(cosv - 0.2f) < 2e-3f) {
                        const float4* ra = (const float4*)(Abase + (size_t)gi * D);
                        const float4* rb = (const float4*)(Abase + (size_t)gj * D);
                        float dot = 0.f;
                        #pragma unroll 4
                        for (int k = 0; k < D / 4; k++) {
                            float4 x = ra[k], y = rb[k];
                            dot += x.x * y.x + x.y * y.y + x.z * y.z + x.w * y.w;
                        }
                        cosv = dot * inv_nn;
                    }
                    float inter = fmaxf(fminf(ei[ii], ej[jj]) - fmaxf(si[ii], sj[jj]), 0.f);
                    float uni   = li[ii] + lj[jj] - inter;
                    float iou   = inter / uni;
                    bool masked = (cosv <= 0.2f) || (iou > 0.2f && gi != gj);
                    if (e == 0) r.x = masked ? 1 : 0; else r.y = masked ? 1 : 0;
                }
                *(uchar2*)&mp[jc] = r;
            }
        }
}

// ---------------- K4: FA2 flash attention (warps over M, P in registers) ----------------
// 8 warps, warp w owns 16 query rows. Bc=64 keys/iter, cp.async double buffer.
// P->A-fragment uses the k-permutation kappa=[0,2,4,6,1,3,5,7] applied identically
// to P regs ({c0,c2,c1,c3}) and V fragment rows (2q, 2q+1): mma sum unchanged.
#define ATP 68
#define KVTILE (64 * ATP)
__global__ __launch_bounds__(256) void k_attn(float* __restrict__ out) {
    extern __shared__ float sm[];
    // [buf][K|V]: K at buf*2*KVTILE, V at buf*2*KVTILE + KVTILE
    uint32_t* S0 = (uint32_t*)sm;

    int i0 = blockIdx.x * 128, head = blockIdx.y, b = blockIdx.z;
    int tid = threadIdx.x, lane = tid & 31, wid = tid >> 5;
    int g = lane >> 2, q = lane & 3;
    const size_t base = (size_t)b * LQ * D + head * DH;

    // ---- stage Q tile via cp.async into buffer 0 (rows 0-63 -> K area, 64-127 -> V area)
    #pragma unroll
    for (int s = 0; s < 8; s++) {
        int f = tid + s * 256;
        int r = f >> 4, c4 = (f & 15) << 2;
        uint32_t dst = (uint32_t)__cvta_generic_to_shared(
            S0 + (r < 64 ? r * ATP : KVTILE + (r - 64) * ATP) + c4);
        cpasync16(dst, &g_Q[base + (size_t)(i0 + r) * D + c4]);
    }
    CP_COMMIT();
    CP_WAIT0();
    __syncthreads();

    // ---- extract Q fragments (already tf32 + 1/8-scaled)
    uint32_t qf[8][4];
    {
        const uint32_t* stage = S0 + ((wid & 4) ? KVTILE : 0);
        int lr = (wid & 3) * 16;
        #pragma unroll
        for (int ks = 0; ks < 8; ks++) {
            qf[ks][0] = stage[(lr + g) * ATP + ks * 8 + q];
            qf[ks][1] = stage[(lr + g + 8) * ATP + ks * 8 + q];
            qf[ks][2] = stage[(lr + g) * ATP + ks * 8 + q + 4];
            qf[ks][3] = stage[(lr + g + 8) * ATP + ks * 8 + q + 4];
        }
    }
    __syncthreads();

    // ---- issue KV tile 0
    #pragma unroll
    for (int s = 0; s < 4; s++) {
        int f = tid + s * 256;
        int r = f >> 4, c4 = (f & 15) << 2;
        size_t ga = base + (size_t)r * D + c4;
        cpasync16((uint32_t)__cvta_generic_to_shared(S0 + r * ATP + c4), &g_K[ga]);
        cpasync16((uint32_t)__cvta_generic_to_shared(S0 + KVTILE + r * ATP + c4), &g_V[ga]);
    }
    CP_COMMIT();

    int rowbase = wid * 16;
    int gi0 = i0 + rowbase;
    float O[8][4] = {};
    float m0 = -1e30f, m1 = -1e30f, l0 = 0.f, l1 = 0.f;

    const unsigned char* mrow0 = g_mask + ((size_t)b * LQ + gi0 + g) * LQ;
    const unsigned char* mrow1 = g_mask + ((size_t)b * LQ + gi0 + g + 8) * LQ;

    for (int j = 0; j < 16; j++) {
        int buf = j & 1;
        const uint32_t* Ks = S0 + buf * 2 * KVTILE;
        const uint32_t* Vs = Ks + KVTILE;

        CP_WAIT0();
        __syncthreads();

        // prefetch next KV tile
        if (j < 15) {
            int nbuf = buf ^ 1;
            uint32_t* Kd = S0 + nbuf * 2 * KVTILE;
            #pragma unroll
            for (int s = 0; s < 4; s++) {
                int f = tid + s * 256;
                int r = f >> 4, c4 = (f & 15) << 2;
                size_t ga = base + (size_t)((j + 1) * 64 + r) * D + c4;
                cpasync16((uint32_t)__cvta_generic_to_shared(Kd + r * ATP + c4), &g_K[ga]);
                cpasync16((uint32_t)__cvta_generic_to_shared(Kd + KVTILE + r * ATP + c4), &g_V[ga]);
            }
            CP_COMMIT();
        }

        // prefetch mask bytes
        int j0 = j * 64;
        uchar2 mk0[8], mk1[8];
        #pragma unroll
        for (int nt = 0; nt < 8; nt++) {
            mk0[nt] = *(const uchar2*)&mrow0[j0 + nt * 8 + 2 * q];
            mk1[nt] = *(const uchar2*)&mrow1[j0 + nt * 8 + 2 * q];
        }

        // S = (Q/8) K^T : 8 n-tiles of 8 keys
        float S[8][4] = {};
        #pragma unroll
        for (int ks = 0; ks < 8; ks++) {
            uint32_t bf[8][2];
            #pragma unroll
            for (int nt = 0; nt < 8; nt++) {
                bf[nt][0] = Ks[(nt * 8 + g) * ATP + ks * 8 + q];
                bf[nt][1] = Ks[(nt * 8 + g) * ATP + ks * 8 + q + 4];
            }
            #pragma unroll
            for (int nt = 0; nt < 8; nt++) mma8(S[nt], qf[ks], bf[nt]);
        }

        // mask
        #pragma unroll
        for (int nt = 0; nt < 8; nt++) {
            if (mk0[nt].x) S[nt][0] = -1e30f;
            if (mk0[nt].y) S[nt][1] = -1e30f;
            if (mk1[nt].x) S[nt][2] = -1e30f;
            if (mk1[nt].y) S[nt][3] = -1e30f;
        }

        // row max (quad shfl over lanes sharing g)
        float mx0 = -1e30f, mx1 = -1e30f;
        #pragma unroll
        for (int nt = 0; nt < 8; nt++) {
            mx0 = fmaxf(mx0, fmaxf(S[nt][0], S[nt][1]));
            mx1 = fmaxf(mx1, fmaxf(S[nt][2], S[nt][3]));
        }
        #pragma unroll
        for (int o = 1; o < 4; o <<= 1) {
            mx0 = fmaxf(mx0, __shfl_xor_sync(0xffffffffu, mx0, o));
            mx1 = fmaxf(mx1, __shfl_xor_sync(0xffffffffu, mx1, o));
        }
        float mn0 = fmaxf(m0, mx0), mn1 = fmaxf(m1, mx1);

        // exp; P stored back into S as tf32 bits
        uint32_t (*P)[4] = (uint32_t(*)[4])S;
        float s0 = 0.f, s1 = 0.f;
        #pragma unroll
        for (int nt = 0; nt < 8; nt++) {
            float p00 = __expf(S[nt][0] - mn0), p01 = __expf(S[nt][1] - mn0);
            float p10 = __expf(S[nt][2] - mn1), p11 = __expf(S[nt][3] - mn1);
            s0 += p00 + p01; s1 += p10 + p11;
            P[nt][0] = f2tf(p00); P[nt][1] = f2tf(p01);
            P[nt][2] = f2tf(p10); P[nt][3] = f2tf(p11);
        }
        #pragma unroll
        for (int o = 1; o < 4; o <<= 1) {
            s0 += __shfl_xor_sync(0xffffffffu, s0, o);
            s1 += __shfl_xor_sync(0xffffffffu, s1, o);
        }
        float sc0 = __expf(m0 - mn0), sc1 = __expf(m1 - mn1);
        l0 = l0 * sc0 + s0; l1 = l1 * sc1 + s1;
        m0 = mn0; m1 = mn1;

        // rescale O
        #pragma unroll
        for (int nt = 0; nt < 8; nt++) {
            O[nt][0] *= sc0; O[nt][1] *= sc0;
            O[nt][2] *= sc1; O[nt][3] *= sc1;
        }

        // O += P V  (k-permuted fragments)
        #pragma unroll
        for (int kc = 0; kc < 8; kc++) {
            uint32_t af[4] = {P[kc][0], P[kc][2], P[kc][1], P[kc][3]};
            uint32_t bf[8][2];
            #pragma unroll
            for (int nt = 0; nt < 8; nt++) {
                bf[nt][0] = Vs[(kc * 8 + 2 * q) * ATP + nt * 8 + g];
                bf[nt][1] = Vs[(kc * 8 + 2 * q + 1) * ATP + nt * 8 + g];
            }
            #pragma unroll
            for (int nt = 0; nt < 8; nt++) mma8(O[nt], af, bf[nt]);
        }
        __syncthreads();
    }

    // epilogue: out = O/l + h
    float inv0 = 1.f / l0, inv1 = 1.f / l1;
    int r0 = gi0 + g, r1 = gi0 + g + 8;
    #pragma unroll
    for (int nt = 0; nt < 8; nt++) {
        int col = head * DH + nt * 8 + 2 * q;
        float2 h0 = *(const float2*)&g_h[((size_t)b * LQ + r0) * D + col];
        float2 h1 = *(const float2*)&g_h[((size_t)b * LQ + r1) * D + col];
        float2 o0, o1;
        o0.x = O[nt][0] * inv0 + h0.x; o0.y = O[nt][1] * inv0 + h0.y;
        o1.x = O[nt][2] * inv1 + h1.x; o1.y = O[nt][3] * inv1 + h1.y;
        *(float2*)&out[((size_t)r0 * BZ + b) * D + col] = o0;
        *(float2*)&out[((size_t)r1 * BZ + b) * D + col] = o1;
    }
}

// ---------------- host ----------------
extern "C" void kernel_launch(void* const* d_in, const int* in_sizes, int n_in,
                              void* d_out, int out_size) {
    const float* query = (const float*)d_in[0];
    const float* seg   = (const float*)d_in[1];
    const float* Wq    = (const float*)d_in[2];
    const float* bq    = (const float*)d_in[3];
    const float* Wk    = (const float*)d_in[4];
    const float* bk    = (const float*)d_in[5];
    const float* Wv    = (const float*)d_in[6];
    const float* bv    = (const float*)d_in[7];
    float* out = (float*)d_out;

    float *hp, *qp, *kp, *vp;
    cudaGetSymbolAddress((void**)&hp, g_h);
    cudaGetSymbolAddress((void**)&qp, g_Q);
    cudaGetSymbolAddress((void**)&kp, g_K);
    cudaGetSymbolAddress((void**)&vp, g_V);

    k_prep<<<BZ * LQ, 128>>>(query);

    dim3 gg(D / 128, BZ * LQ / 128, 3);   // (4, 64, 3)
    k_gemm_qkv<<<gg, 256>>>(hp, Wq, Wk, Wv, bq, bk, bv, qp, kp, vp);

    dim3 gm(LQ / 128, LQ / 128, BZ);      // (8, 8, 8)
    k_mask<<<gm, 256>>>(seg);

    int smem = 4 * KVTILE * (int)sizeof(float);   // 2 buffers x (K + V) = 69632 B
    cudaFuncSetAttribute(k_attn, cudaFuncAttributeMaxDynamicSharedMemorySize, smem);
    dim3 ga(LQ / 128, NH, BZ);            // (8, 8, 8)
    k_attn<<<ga, 256, smem>>>(out);
}

// round 7
// speedup vs baseline: 3.3745x; 1.0216x over previous
#include <cuda_runtime.h>
#include <stdint.h>
#include <math.h>

#define BZ 8
#define LQ 1024
#define D  512
#define NH 8
#define DH 64

// ---------------- scratch ----------------
__device__ float g_h[BZ * LQ * D];
__device__ float g_Q[BZ * LQ * D];   // tf32 bits, pre-scaled by 1/8
__device__ float g_K[BZ * LQ * D];   // tf32 bits
__device__ float g_V[BZ * LQ * D];   // tf32 bits
__device__ float g_norm[BZ * LQ];
__device__ unsigned char g_mask[(size_t)BZ * LQ * LQ];  // 1 = masked

// ---------------- helpers ----------------
__device__ __forceinline__ uint32_t f2tf(float f) {
    uint32_t u;
    asm("cvt.rna.tf32.f32 %0, %1;" : "=r"(u) : "f"(f));
    return u;
}
__device__ __forceinline__ void mma8(float* d, const uint32_t* a, const uint32_t* b) {
    asm volatile(
        "mma.sync.aligned.m16n8k8.row.col.f32.tf32.tf32.f32 "
        "{%0,%1,%2,%3},{%4,%5,%6,%7},{%8,%9},{%0,%1,%2,%3};\n"
        : "+f"(d[0]), "+f"(d[1]), "+f"(d[2]), "+f"(d[3])
        : "r"(a[0]), "r"(a[1]), "r"(a[2]), "r"(a[3]), "r"(b[0]), "r"(b[1]));
}
__device__ __forceinline__ void cpasync16(uint32_t saddr, const void* g) {
    asm volatile("cp.async.cg.shared.global [%0], [%1], 16;" :: "r"(saddr), "l"(g));
}
#define CP_COMMIT() asm volatile("cp.async.commit_group;")
#define CP_WAIT0()  asm volatile("cp.async.wait_group 0;")

// ---------------- K1: transpose + row norms ----------------
__global__ __launch_bounds__(128) void k_prep(const float* __restrict__ q) {
    int row = blockIdx.x;              // r = i*BZ + b
    int i = row >> 3, b = row & 7;
    int tid = threadIdx.x, lane = tid & 31, wid = tid >> 5;
    float4 v = ((const float4*)(q + (size_t)row * D))[tid];
    ((float4*)g_h)[(size_t)(b * LQ + i) * (D / 4) + tid] = v;
    float s = v.x * v.x + v.y * v.y + v.z * v.z + v.w * v.w;
    #pragma unroll
    for (int o = 16; o; o >>= 1) s += __shfl_xor_sync(0xffffffffu, s, o);
    __shared__ float ws[4];
    if (lane == 0) ws[wid] = s;
    __syncthreads();
    if (tid == 0)
        g_norm[b * LQ + i] = fmaxf(sqrtf(ws[0] + ws[1] + ws[2] + ws[3]), 1e-8f);
}

// ---------------- K2: fused QKV tf32 GEMM, epilogue stores tf32 bits ----------------
#define KP 20
__global__ __launch_bounds__(256, 2) void k_gemm_qkv(
    const float* __restrict__ A,
    const float* __restrict__ W0, const float* __restrict__ W1, const float* __restrict__ W2,
    const float* __restrict__ b0, const float* __restrict__ b1, const float* __restrict__ b2,
    float* __restrict__ C0, float* __restrict__ C1, float* __restrict__ C2)
{
    const int N = D, K = D;
    int z = blockIdx.z;
    const float* B    = (z == 0) ? W0 : (z == 1) ? W1 : W2;
    const float* bias = (z == 0) ? b0 : (z == 1) ? b1 : b2;
    float*       C    = (z == 0) ? C0 : (z == 1) ? C1 : C2;
    float oscale = (z == 0) ? 0.125f : 1.0f;

    __shared__ uint32_t As[2][128][KP];
    __shared__ uint32_t Bs[2][128][KP];
    int tid = threadIdx.x, lane = tid & 31, wid = tid >> 5;
    int g = lane >> 2, q = lane & 3;
    int wm = wid >> 2, wn = wid & 3;
    int m0 = blockIdx.y * 128, n0 = blockIdx.x * 128;

    int lrow = tid >> 1, lc = (tid & 1) * 8;
    const float* Ap = A + (size_t)(m0 + lrow) * K + lc;
    const float* Bp = B + (size_t)(n0 + lrow) * K + lc;

    float4 a0r = *(const float4*)Ap, a1r = *(const float4*)(Ap + 4);
    float4 b0r = *(const float4*)Bp, b1r = *(const float4*)(Bp + 4);
    {
        uint32_t* d = &As[0][lrow][lc];
        d[0]=f2tf(a0r.x); d[1]=f2tf(a0r.y); d[2]=f2tf(a0r.z); d[3]=f2tf(a0r.w);
        d[4]=f2tf(a1r.x); d[5]=f2tf(a1r.y); d[6]=f2tf(a1r.z); d[7]=f2tf(a1r.w);
        uint32_t* e = &Bs[0][lrow][lc];
        e[0]=f2tf(b0r.x); e[1]=f2tf(b0r.y); e[2]=f2tf(b0r.z); e[3]=f2tf(b0r.w);
        e[4]=f2tf(b1r.x); e[5]=f2tf(b1r.y); e[6]=f2tf(b1r.z); e[7]=f2tf(b1r.w);
    }
    __syncthreads();

    float acc[4][4][4] = {};
    int nP = K / 16, buf = 0;
    for (int p = 0; p < nP; p++) {
        if (p + 1 < nP) {
            const float* Ap2 = Ap + (p + 1) * 16;
            const float* Bp2 = Bp + (p + 1) * 16;
            a0r = *(const float4*)Ap2; a1r = *(const float4*)(Ap2 + 4);
            b0r = *(const float4*)Bp2; b1r = *(const float4*)(Bp2 + 4);
        }
        #pragma unroll
        for (int ks = 0; ks < 2; ks++) {
            int k8 = ks * 8;
            uint32_t af[4][4], bf[4][2];
            #pragma unroll
            for (int mt = 0; mt < 4; mt++) {
                int mb = wm * 64 + mt * 16;
                af[mt][0] = As[buf][mb + g][k8 + q];
                af[mt][1] = As[buf][mb + g + 8][k8 + q];
                af[mt][2] = As[buf][mb + g][k8 + q + 4];
                af[mt][3] = As[buf][mb + g + 8][k8 + q + 4];
            }
            #pragma unroll
            for (int nt = 0; nt < 4; nt++) {
                int nb = wn * 32 + nt * 8 + g;
                bf[nt][0] = Bs[buf][nb][k8 + q];
                bf[nt][1] = Bs[buf][nb][k8 + q + 4];
            }
            #pragma unroll
            for (int mt = 0; mt < 4; mt++)
                #pragma unroll
                for (int nt = 0; nt < 4; nt++) mma8(acc[mt][nt], af[mt], bf[nt]);
        }
        if (p + 1 < nP) {
            int nb = buf ^ 1;
            uint32_t* d = &As[nb][lrow][lc];
            d[0]=f2tf(a0r.x); d[1]=f2tf(a0r.y); d[2]=f2tf(a0r.z); d[3]=f2tf(a0r.w);
            d[4]=f2tf(a1r.x); d[5]=f2tf(a1r.y); d[6]=f2tf(a1r.z); d[7]=f2tf(a1r.w);
            uint32_t* e = &Bs[nb][lrow][lc];
            e[0]=f2tf(b0r.x); e[1]=f2tf(b0r.y); e[2]=f2tf(b0r.z); e[3]=f2tf(b0r.w);
            e[4]=f2tf(b1r.x); e[5]=f2tf(b1r.y); e[6]=f2tf(b1r.z); e[7]=f2tf(b1r.w);
            buf = nb;
        }
        __syncthreads();
    }

    // epilogue: C = tf32( (acc + bias) * oscale )
    #pragma unroll
    for (int mt = 0; mt < 4; mt++)
        #pragma unroll
        for (int h2 = 0; h2 < 2; h2++) {
            int m = m0 + wm * 64 + mt * 16 + g + h2 * 8;
            #pragma unroll
            for (int nt = 0; nt < 4; nt++) {
                int n = n0 + wn * 32 + nt * 8 + 2 * q;
                float2 v;
                v.x = __uint_as_float(f2tf((acc[mt][nt][h2 * 2 + 0] + bias[n]) * oscale));
                v.y = __uint_as_float(f2tf((acc[mt][nt][h2 * 2 + 1] + bias[n + 1]) * oscale));
                *(float2*)&C[(size_t)m * N + n] = v;
            }
        }
}

// ---------------- K3: mask via single tf32 Gram + fp32 fixup near threshold ----------------
__global__ __launch_bounds__(256, 2) void k_mask(const float* __restrict__ seg) {
    __shared__ uint32_t As[2][128][KP];
    __shared__ uint32_t Bs[2][128][KP];
    __shared__ float si[128], ei[128], li[128], ni[128];
    __shared__ float sj[128], ej[128], lj[128], nj[128];
    int b = blockIdx.z;
    int i0 = blockIdx.y * 128, j0 = blockIdx.x * 128;
    int tid = threadIdx.x, lane = tid & 31, wid = tid >> 5;
    int g = lane >> 2, q = lane & 3;
    int wm = wid >> 2, wn = wid & 3;

    if (tid < 128) {
        int gi = b * LQ + i0 + tid;
        float c = seg[gi * 2], l = seg[gi * 2 + 1];
        si[tid] = c - 0.5f * l; ei[tid] = c + 0.5f * l; li[tid] = l;
        ni[tid] = g_norm[gi];
    } else {
        int t = tid - 128;
        int gj = b * LQ + j0 + t;
        float c = seg[gj * 2], l = seg[gj * 2 + 1];
        sj[t] = c - 0.5f * l; ej[t] = c + 0.5f * l; lj[t] = l;
        nj[t] = g_norm[gj];
    }

    const float* Abase = g_h + (size_t)b * LQ * D;
    int lrow = tid >> 1, lc = (tid & 1) * 8;
    const float* Ap = Abase + (size_t)(i0 + lrow) * D + lc;
    const float* Bp = Abase + (size_t)(j0 + lrow) * D + lc;

    float4 a0r = *(const float4*)Ap, a1r = *(const float4*)(Ap + 4);
    float4 b0r = *(const float4*)Bp, b1r = *(const float4*)(Bp + 4);
    {
        uint32_t* d = &As[0][lrow][lc];
        d[0]=f2tf(a0r.x); d[1]=f2tf(a0r.y); d[2]=f2tf(a0r.z); d[3]=f2tf(a0r.w);
        d[4]=f2tf(a1r.x); d[5]=f2tf(a1r.y); d[6]=f2tf(a1r.z); d[7]=f2tf(a1r.w);
        uint32_t* e = &Bs[0][lrow][lc];
        e[0]=f2tf(b0r.x); e[1]=f2tf(b0r.y); e[2]=f2tf(b0r.z); e[3]=f2tf(b0r.w);
        e[4]=f2tf(b1r.x); e[5]=f2tf(b1r.y); e[6]=f2tf(b1r.z); e[7]=f2tf(b1r.w);
    }
    __syncthreads();

    float acc[4][4][4] = {};
    int nP = D / 16, buf = 0;
    for (int p = 0; p < nP; p++) {
        if (p + 1 < nP) {
            const float* Ap2 = Ap + (p + 1) * 16;
            const float* Bp2 = Bp + (p + 1) * 16;
            a0r = *(const float4*)Ap2; a1r = *(const float4*)(Ap2 + 4);
            b0r = *(const float4*)Bp2; b1r = *(const float4*)(Bp2 + 4);
        }
        #pragma unroll
        for (int ks = 0; ks < 2; ks++) {
            int k8 = ks * 8;
            uint32_t af[4][4], bf[4][2];
            #pragma unroll
            for (int mt = 0; mt < 4; mt++) {
                int mb = wm * 64 + mt * 16;
                af[mt][0] = As[buf][mb + g][k8 + q];
                af[mt][1] = As[buf][mb + g + 8][k8 + q];
                af[mt][2] = As[buf][mb + g][k8 + q + 4];
                af[mt][3] = As[buf][mb + g + 8][k8 + q + 4];
            }
            #pragma unroll
            for (int nt = 0; nt < 4; nt++) {
                int nb = wn * 32 + nt * 8 + g;
                bf[nt][0] = Bs[buf][nb][k8 + q];
                bf[nt][1] = Bs[buf][nb][k8 + q + 4];
            }
            #pragma unroll
            for (int mt = 0; mt < 4; mt++)
                #pragma unroll
                for (int nt = 0; nt < 4; nt++) mma8(acc[mt][nt], af[mt], bf[nt]);
        }
        if (p + 1 < nP) {
            int nb = buf ^ 1;
            uint32_t* d = &As[nb][lrow][lc];
            d[0]=f2tf(a0r.x); d[1]=f2tf(a0r.y); d[2]=f2tf(a0r.z); d[3]=f2tf(a0r.w);
            d[4]=f2tf(a1r.x); d[5]=f2tf(a1r.y); d[6]=f2tf(a1r.z); d[7]=f2tf(a1r.w);
            uint32_t* e = &Bs[nb][lrow][lc];
            e[0]=f2tf(b0r.x); e[1]=f2tf(b0r.y); e[2]=f2tf(b0r.z); e[3]=f2tf(b0r.w);
            e[4]=f2tf(b1r.x); e[5]=f2tf(b1r.y); e[6]=f2tf(b1r.z); e[7]=f2tf(b1r.w);
            buf = nb;
        }
        __syncthreads();
    }

    #pragma unroll
    for (int mt = 0; mt < 4; mt++)
        #pragma unroll
        for (int h2 = 0; h2 < 2; h2++) {
            int ii = wm * 64 + mt * 16 + g + h2 * 8;
            int gi = i0 + ii;
            unsigned char* mp = g_mask + ((size_t)b * LQ + gi) * LQ + j0;
            #pragma unroll
            for (int nt = 0; nt < 4; nt++) {
                int jc = wn * 32 + nt * 8 + 2 * q;
                uchar2 r;
                #pragma unroll
                for (int e = 0; e < 2; e++) {
                    int jj = jc + e, gj = j0 + jj;
                    float inv_nn = 1.f / (ni[ii] * nj[jj]);
                    float cosv = acc[mt][nt][h2 * 2 + e] * inv_nn;
                    if (fabsf(cosv - 0.2f) < 2e-3f) {
                        const float4* ra = (const float4*)(Abase + (size_t)gi * D);
                        const float4* rb = (const float4*)(Abase + (size_t)gj * D);
                        float dot = 0.f;
                        #pragma unroll 4
                        for (int k = 0; k < D / 4; k++) {
                            float4 x = ra[k], y = rb[k];
                            dot += x.x * y.x + x.y * y.y + x.z * y.z + x.w * y.w;
                        }
                        cosv = dot * inv_nn;
                    }
                    float inter = fmaxf(fminf(ei[ii], ej[jj]) - fmaxf(si[ii], sj[jj]), 0.f);
                    float uni   = li[ii] + lj[jj] - inter;
                    float iou   = inter / uni;
                    bool masked = (cosv <= 0.2f) || (iou > 0.2f && gi != gj);
                    if (e == 0) r.x = masked ? 1 : 0; else r.y = masked ? 1 : 0;
                }
                *(uchar2*)&mp[jc] = r;
            }
        }
}

// ---------------- K4: FA2 flash attention, Q smem-resident, 2 CTAs/SM ----------------
#define ATP 68
#define KVTILE (64 * ATP)
__global__ __launch_bounds__(256, 2) void k_attn(float* __restrict__ out) {
    extern __shared__ float sm[];
    uint32_t* Qs = (uint32_t*)sm;          // 128*ATP, persistent
    uint32_t* KV = Qs + 128 * ATP;         // 2 buffers x (K tile + V tile)

    int i0 = blockIdx.x * 128, head = blockIdx.y, b = blockIdx.z;
    int tid = threadIdx.x, lane = tid & 31, wid = tid >> 5;
    int g = lane >> 2, q = lane & 3;
    const size_t base = (size_t)b * LQ * D + head * DH;

    // stage Q tile (tf32 bits, pre-scaled) into Qs
    #pragma unroll
    for (int s = 0; s < 8; s++) {
        int f = tid + s * 256;
        int r = f >> 4, c4 = (f & 15) << 2;
        cpasync16((uint32_t)__cvta_generic_to_shared(Qs + r * ATP + c4),
                  &g_Q[base + (size_t)(i0 + r) * D + c4]);
    }
    CP_COMMIT();

    // issue KV tile 0
    #pragma unroll
    for (int s = 0; s < 4; s++) {
        int f = tid + s * 256;
        int r = f >> 4, c4 = (f & 15) << 2;
        size_t ga = base + (size_t)r * D + c4;
        cpasync16((uint32_t)__cvta_generic_to_shared(KV + r * ATP + c4), &g_K[ga]);
        cpasync16((uint32_t)__cvta_generic_to_shared(KV + KVTILE + r * ATP + c4), &g_V[ga]);
    }
    CP_COMMIT();

    int lr = wid * 16;                      // this warp's 16 query rows
    int gi0 = i0 + lr;
    float O[8][4] = {};
    float m0 = -1e30f, m1 = -1e30f, l0 = 0.f, l1 = 0.f;

    const unsigned char* mrow0 = g_mask + ((size_t)b * LQ + gi0 + g) * LQ;
    const unsigned char* mrow1 = g_mask + ((size_t)b * LQ + gi0 + g + 8) * LQ;

    for (int j = 0; j < 16; j++) {
        int buf = j & 1;
        const uint32_t* Ks = KV + buf * 2 * KVTILE;
        const uint32_t* Vs = Ks + KVTILE;

        CP_WAIT0();
        __syncthreads();

        // prefetch next KV tile into the other buffer
        if (j < 15) {
            uint32_t* Kd = KV + (buf ^ 1) * 2 * KVTILE;
            #pragma unroll
            for (int s = 0; s < 4; s++) {
                int f = tid + s * 256;
                int r = f >> 4, c4 = (f & 15) << 2;
                size_t ga = base + (size_t)((j + 1) * 64 + r) * D + c4;
                cpasync16((uint32_t)__cvta_generic_to_shared(Kd + r * ATP + c4), &g_K[ga]);
                cpasync16((uint32_t)__cvta_generic_to_shared(Kd + KVTILE + r * ATP + c4), &g_V[ga]);
            }
            CP_COMMIT();
        }

        // mask bytes
        int j0 = j * 64;
        uchar2 mk0[8], mk1[8];
        #pragma unroll
        for (int nt = 0; nt < 8; nt++) {
            mk0[nt] = *(const uchar2*)&mrow0[j0 + nt * 8 + 2 * q];
            mk1[nt] = *(const uchar2*)&mrow1[j0 + nt * 8 + 2 * q];
        }

        // S = (Q/8) K^T, Q fragment re-loaded from smem per k-step
        float S[8][4] = {};
        #pragma unroll
        for (int ks = 0; ks < 8; ks++) {
            uint32_t af[4];
            af[0] = Qs[(lr + g) * ATP + ks * 8 + q];
            af[1] = Qs[(lr + g + 8) * ATP + ks * 8 + q];
            af[2] = Qs[(lr + g) * ATP + ks * 8 + q + 4];
            af[3] = Qs[(lr + g + 8) * ATP + ks * 8 + q + 4];
            uint32_t bf[8][2];
            #pragma unroll
            for (int nt = 0; nt < 8; nt++) {
                bf[nt][0] = Ks[(nt * 8 + g) * ATP + ks * 8 + q];
                bf[nt][1] = Ks[(nt * 8 + g) * ATP + ks * 8 + q + 4];
            }
            #pragma unroll
            for (int nt = 0; nt < 8; nt++) mma8(S[nt], af, bf[nt]);
        }

        // mask
        #pragma unroll
        for (int nt = 0; nt < 8; nt++) {
            if (mk0[nt].x) S[nt][0] = -1e30f;
            if (mk0[nt].y) S[nt][1] = -1e30f;
            if (mk1[nt].x) S[nt][2] = -1e30f;
            if (mk1[nt].y) S[nt][3] = -1e30f;
        }

        // quad-reduced online softmax
        float mx0 = -1e30f, mx1 = -1e30f;
        #pragma unroll
        for (int nt = 0; nt < 8; nt++) {
            mx0 = fmaxf(mx0, fmaxf(S[nt][0], S[nt][1]));
            mx1 = fmaxf(mx1, fmaxf(S[nt][2], S[nt][3]));
        }
        #pragma unroll
        for (int o = 1; o < 4; o <<= 1) {
            mx0 = fmaxf(mx0, __shfl_xor_sync(0xffffffffu, mx0, o));
            mx1 = fmaxf(mx1, __shfl_xor_sync(0xffffffffu, mx1, o));
        }
        float mn0 = fmaxf(m0, mx0), mn1 = fmaxf(m1, mx1);

        uint32_t (*P)[4] = (uint32_t(*)[4])S;
        float s0 = 0.f, s1 = 0.f;
        #pragma unroll
        for (int nt = 0; nt < 8; nt++) {
            float p00 = __expf(S[nt][0] - mn0), p01 = __expf(S[nt][1] - mn0);
            float p10 = __expf(S[nt][2] - mn1), p11 = __expf(S[nt][3] - mn1);
            s0 += p00 + p01; s1 += p10 + p11;
            P[nt][0] = f2tf(p00); P[nt][1] = f2tf(p01);
            P[nt][2] = f2tf(p10); P[nt][3] = f2tf(p11);
        }
        #pragma unroll
        for (int o = 1; o < 4; o <<= 1) {
            s0 += __shfl_xor_sync(0xffffffffu, s0, o);
            s1 += __shfl_xor_sync(0xffffffffu, s1, o);
        }
        float sc0 = __expf(m0 - mn0), sc1 = __expf(m1 - mn1);
        l0 = l0 * sc0 + s0; l1 = l1 * sc1 + s1;
        m0 = mn0; m1 = mn1;

        #pragma unroll
        for (int nt = 0; nt < 8; nt++) {
            O[nt][0] *= sc0; O[nt][1] *= sc0;
            O[nt][2] *= sc1; O[nt][3] *= sc1;
        }

        // O += P V (k-permuted fragments: identical permutation on A regs and V rows)
        #pragma unroll
        for (int kc = 0; kc < 8; kc++) {
            uint32_t af[4] = {P[kc][0], P[kc][2], P[kc][1], P[kc][3]};
            uint32_t bf[8][2];
            #pragma unroll
            for (int nt = 0; nt < 8; nt++) {
                bf[nt][0] = Vs[(kc * 8 + 2 * q) * ATP + nt * 8 + g];
                bf[nt][1] = Vs[(kc * 8 + 2 * q + 1) * ATP + nt * 8 + g];
            }
            #pragma unroll
            for (int nt = 0; nt < 8; nt++) mma8(O[nt], af, bf[nt]);
        }
    }

    // epilogue: out = O/l + h
    float inv0 = 1.f / l0, inv1 = 1.f / l1;
    int r0 = gi0 + g, r1 = gi0 + g + 8;
    #pragma unroll
    for (int nt = 0; nt < 8; nt++) {
        int col = head * DH + nt * 8 + 2 * q;
        float2 h0 = *(const float2*)&g_h[((size_t)b * LQ + r0) * D + col];
        float2 h1 = *(const float2*)&g_h[((size_t)b * LQ + r1) * D + col];
        float2 o0, o1;
        o0.x = O[nt][0] * inv0 + h0.x; o0.y = O[nt][1] * inv0 + h0.y;
        o1.x = O[nt][2] * inv1 + h1.x; o1.y = O[nt][3] * inv1 + h1.y;
        *(float2*)&out[((size_t)r0 * BZ + b) * D + col] = o0;
        *(float2*)&out[((size_t)r1 * BZ + b) * D + col] = o1;
    }
}

// ---------------- host ----------------
extern "C" void kernel_launch(void* const* d_in, const int* in_sizes, int n_in,
                              void* d_out, int out_size) {
    const float* query = (const float*)d_in[0];
    const float* seg   = (const float*)d_in[1];
    const float* Wq    = (const float*)d_in[2];
    const float* bq    = (const float*)d_in[3];
    const float* Wk    = (const float*)d_in[4];
    const float* bk    = (const float*)d_in[5];
    const float* Wv    = (const float*)d_in[6];
    const float* bv    = (const float*)d_in[7];
    float* out = (float*)d_out;

    float *hp, *qp, *kp, *vp;
    cudaGetSymbolAddress((void**)&hp, g_h);
    cudaGetSymbolAddress((void**)&qp, g_Q);
    cudaGetSymbolAddress((void**)&kp, g_K);
    cudaGetSymbolAddress((void**)&vp, g_V);

    k_prep<<<BZ * LQ, 128>>>(query);

    dim3 gg(D / 128, BZ * LQ / 128, 3);   // (4, 64, 3)
    k_gemm_qkv<<<gg, 256>>>(hp, Wq, Wk, Wv, bq, bk, bv, qp, kp, vp);

    dim3 gm(LQ / 128, LQ / 128, BZ);      // (8, 8, 8)
    k_mask<<<gm, 256>>>(seg);

    int smem = (128 * ATP + 4 * KVTILE) * (int)sizeof(float);   // 104448 B
    cudaFuncSetAttribute(k_attn, cudaFuncAttributeMaxDynamicSharedMemorySize, smem);
    dim3 ga(LQ / 128, NH, BZ);            // (8, 8, 8)
    k_attn<<<ga, 256, smem>>>(out);
}

// round 8
// speedup vs baseline: 5.2168x; 1.5459x over previous
#include <cuda_runtime.h>
#include <stdint.h>
#include <math.h>

#define BZ 8
#define LQ 1024
#define D  512
#define NH 8
#define DH 64

// ---------------- scratch ----------------
__device__ float g_h[BZ * LQ * D];
__device__ float g_Q[BZ * LQ * D];   // tf32 bits, pre-scaled by 1/8
__device__ float g_K[BZ * LQ * D];   // tf32 bits
__device__ float g_V[BZ * LQ * D];   // tf32 bits
__device__ float g_norm[BZ * LQ];
__device__ unsigned char g_mask[(size_t)BZ * LQ * LQ];  // 1 = masked

// ---------------- helpers ----------------
__device__ __forceinline__ uint32_t f2tf(float f) {
    uint32_t u;
    asm("cvt.rna.tf32.f32 %0, %1;" : "=r"(u) : "f"(f));
    return u;
}
__device__ __forceinline__ void mma8(float* d, const uint32_t* a, const uint32_t* b) {
    asm volatile(
        "mma.sync.aligned.m16n8k8.row.col.f32.tf32.tf32.f32 "
        "{%0,%1,%2,%3},{%4,%5,%6,%7},{%8,%9},{%0,%1,%2,%3};\n"
        : "+f"(d[0]), "+f"(d[1]), "+f"(d[2]), "+f"(d[3])
        : "r"(a[0]), "r"(a[1]), "r"(a[2]), "r"(a[3]), "r"(b[0]), "r"(b[1]));
}
__device__ __forceinline__ void cpasync16(uint32_t saddr, const void* g) {
    asm volatile("cp.async.cg.shared.global [%0], [%1], 16;" :: "r"(saddr), "l"(g));
}
#define CP_COMMIT() asm volatile("cp.async.commit_group;")
#define CP_WAIT0()  asm volatile("cp.async.wait_group 0;")

// ---------------- K1: transpose + row norms ----------------
__global__ __launch_bounds__(128) void k_prep(const float* __restrict__ q) {
    int row = blockIdx.x;              // r = i*BZ + b
    int i = row >> 3, b = row & 7;
    int tid = threadIdx.x, lane = tid & 31, wid = tid >> 5;
    float4 v = ((const float4*)(q + (size_t)row * D))[tid];
    ((float4*)g_h)[(size_t)(b * LQ + i) * (D / 4) + tid] = v;
    float s = v.x * v.x + v.y * v.y + v.z * v.z + v.w * v.w;
    #pragma unroll
    for (int o = 16; o; o >>= 1) s += __shfl_xor_sync(0xffffffffu, s, o);
    __shared__ float ws[4];
    if (lane == 0) ws[wid] = s;
    __syncthreads();
    if (tid == 0)
        g_norm[b * LQ + i] = fmaxf(sqrtf(ws[0] + ws[1] + ws[2] + ws[3]), 1e-8f);
}

// ---------------- K2: fused QKV tf32 GEMM, epilogue stores tf32 bits ----------------
#define KP 20
__global__ __launch_bounds__(256, 2) void k_gemm_qkv(
    const float* __restrict__ A,
    const float* __restrict__ W0, const float* __restrict__ W1, const float* __restrict__ W2,
    const float* __restrict__ b0, const float* __restrict__ b1, const float* __restrict__ b2,
    float* __restrict__ C0, float* __restrict__ C1, float* __restrict__ C2)
{
    const int N = D, K = D;
    int z = blockIdx.z;
    const float* B    = (z == 0) ? W0 : (z == 1) ? W1 : W2;
    const float* bias = (z == 0) ? b0 : (z == 1) ? b1 : b2;
    float*       C    = (z == 0) ? C0 : (z == 1) ? C1 : C2;
    float oscale = (z == 0) ? 0.125f : 1.0f;

    __shared__ uint32_t As[2][128][KP];
    __shared__ uint32_t Bs[2][128][KP];
    int tid = threadIdx.x, lane = tid & 31, wid = tid >> 5;
    int g = lane >> 2, q = lane & 3;
    int wm = wid >> 2, wn = wid & 3;
    int m0 = blockIdx.y * 128, n0 = blockIdx.x * 128;

    int lrow = tid >> 1, lc = (tid & 1) * 8;
    const float* Ap = A + (size_t)(m0 + lrow) * K + lc;
    const float* Bp = B + (size_t)(n0 + lrow) * K + lc;

    float4 a0r = *(const float4*)Ap, a1r = *(const float4*)(Ap + 4);
    float4 b0r = *(const float4*)Bp, b1r = *(const float4*)(Bp + 4);
    {
        uint32_t* d = &As[0][lrow][lc];
        d[0]=f2tf(a0r.x); d[1]=f2tf(a0r.y); d[2]=f2tf(a0r.z); d[3]=f2tf(a0r.w);
        d[4]=f2tf(a1r.x); d[5]=f2tf(a1r.y); d[6]=f2tf(a1r.z); d[7]=f2tf(a1r.w);
        uint32_t* e = &Bs[0][lrow][lc];
        e[0]=f2tf(b0r.x); e[1]=f2tf(b0r.y); e[2]=f2tf(b0r.z); e[3]=f2tf(b0r.w);
        e[4]=f2tf(b1r.x); e[5]=f2tf(b1r.y); e[6]=f2tf(b1r.z); e[7]=f2tf(b1r.w);
    }
    __syncthreads();

    float acc[4][4][4] = {};
    int nP = K / 16, buf = 0;
    for (int p = 0; p < nP; p++) {
        if (p + 1 < nP) {
            const float* Ap2 = Ap + (p + 1) * 16;
            const float* Bp2 = Bp + (p + 1) * 16;
            a0r = *(const float4*)Ap2; a1r = *(const float4*)(Ap2 + 4);
            b0r = *(const float4*)Bp2; b1r = *(const float4*)(Bp2 + 4);
        }
        #pragma unroll
        for (int ks = 0; ks < 2; ks++) {
            int k8 = ks * 8;
            uint32_t af[4][4], bf[4][2];
            #pragma unroll
            for (int mt = 0; mt < 4; mt++) {
                int mb = wm * 64 + mt * 16;
                af[mt][0] = As[buf][mb + g][k8 + q];
                af[mt][1] = As[buf][mb + g + 8][k8 + q];
                af[mt][2] = As[buf][mb + g][k8 + q + 4];
                af[mt][3] = As[buf][mb + g + 8][k8 + q + 4];
            }
            #pragma unroll
            for (int nt = 0; nt < 4; nt++) {
                int nb = wn * 32 + nt * 8 + g;
                bf[nt][0] = Bs[buf][nb][k8 + q];
                bf[nt][1] = Bs[buf][nb][k8 + q + 4];
            }
            #pragma unroll
            for (int mt = 0; mt < 4; mt++)
                #pragma unroll
                for (int nt = 0; nt < 4; nt++) mma8(acc[mt][nt], af[mt], bf[nt]);
        }
        if (p + 1 < nP) {
            int nb = buf ^ 1;
            uint32_t* d = &As[nb][lrow][lc];
            d[0]=f2tf(a0r.x); d[1]=f2tf(a0r.y); d[2]=f2tf(a0r.z); d[3]=f2tf(a0r.w);
            d[4]=f2tf(a1r.x); d[5]=f2tf(a1r.y); d[6]=f2tf(a1r.z); d[7]=f2tf(a1r.w);
            uint32_t* e = &Bs[nb][lrow][lc];
            e[0]=f2tf(b0r.x); e[1]=f2tf(b0r.y); e[2]=f2tf(b0r.z); e[3]=f2tf(b0r.w);
            e[4]=f2tf(b1r.x); e[5]=f2tf(b1r.y); e[6]=f2tf(b1r.z); e[7]=f2tf(b1r.w);
            buf = nb;
        }
        __syncthreads();
    }

    #pragma unroll
    for (int mt = 0; mt < 4; mt++)
        #pragma unroll
        for (int h2 = 0; h2 < 2; h2++) {
            int m = m0 + wm * 64 + mt * 16 + g + h2 * 8;
            #pragma unroll
            for (int nt = 0; nt < 4; nt++) {
                int n = n0 + wn * 32 + nt * 8 + 2 * q;
                float2 v;
                v.x = __uint_as_float(f2tf((acc[mt][nt][h2 * 2 + 0] + bias[n]) * oscale));
                v.y = __uint_as_float(f2tf((acc[mt][nt][h2 * 2 + 1] + bias[n + 1]) * oscale));
                *(float2*)&C[(size_t)m * N + n] = v;
            }
        }
}

// ---------------- K3: mask (lower-triangle tiles only + mirrored write) ----------------
__global__ __launch_bounds__(256, 2) void k_mask(const float* __restrict__ seg) {
    __shared__ uint32_t As[2][128][KP];
    __shared__ uint32_t Bs[2][128][KP];
    __shared__ float si[128], ei[128], li[128], ni[128];
    __shared__ float sj[128], ej[128], lj[128], nj[128];
    int b = blockIdx.z;
    // decode lower-triangle pair (it, jt), it >= jt, from linear index
    int t = blockIdx.x;
    int it = 0;
    while ((it + 1) * (it + 2) / 2 <= t) it++;
    int jt = t - it * (it + 1) / 2;
    int i0 = it * 128, j0 = jt * 128;

    int tid = threadIdx.x, lane = tid & 31, wid = tid >> 5;
    int g = lane >> 2, q = lane & 3;
    int wm = wid >> 2, wn = wid & 3;

    if (tid < 128) {
        int gi = b * LQ + i0 + tid;
        float c = seg[gi * 2], l = seg[gi * 2 + 1];
        si[tid] = c - 0.5f * l; ei[tid] = c + 0.5f * l; li[tid] = l;
        ni[tid] = g_norm[gi];
    } else {
        int tt = tid - 128;
        int gj = b * LQ + j0 + tt;
        float c = seg[gj * 2], l = seg[gj * 2 + 1];
        sj[tt] = c - 0.5f * l; ej[tt] = c + 0.5f * l; lj[tt] = l;
        nj[tt] = g_norm[gj];
    }

    const float* Abase = g_h + (size_t)b * LQ * D;
    int lrow = tid >> 1, lc = (tid & 1) * 8;
    const float* Ap = Abase + (size_t)(i0 + lrow) * D + lc;
    const float* Bp = Abase + (size_t)(j0 + lrow) * D + lc;

    float4 a0r = *(const float4*)Ap, a1r = *(const float4*)(Ap + 4);
    float4 b0r = *(const float4*)Bp, b1r = *(const float4*)(Bp + 4);
    {
        uint32_t* d = &As[0][lrow][lc];
        d[0]=f2tf(a0r.x); d[1]=f2tf(a0r.y); d[2]=f2tf(a0r.z); d[3]=f2tf(a0r.w);
        d[4]=f2tf(a1r.x); d[5]=f2tf(a1r.y); d[6]=f2tf(a1r.z); d[7]=f2tf(a1r.w);
        uint32_t* e = &Bs[0][lrow][lc];
        e[0]=f2tf(b0r.x); e[1]=f2tf(b0r.y); e[2]=f2tf(b0r.z); e[3]=f2tf(b0r.w);
        e[4]=f2tf(b1r.x); e[5]=f2tf(b1r.y); e[6]=f2tf(b1r.z); e[7]=f2tf(b1r.w);
    }
    __syncthreads();

    float acc[4][4][4] = {};
    int nP = D / 16, buf = 0;
    for (int p = 0; p < nP; p++) {
        if (p + 1 < nP) {
            const float* Ap2 = Ap + (p + 1) * 16;
            const float* Bp2 = Bp + (p + 1) * 16;
            a0r = *(const float4*)Ap2; a1r = *(const float4*)(Ap2 + 4);
            b0r = *(const float4*)Bp2; b1r = *(const float4*)(Bp2 + 4);
        }
        #pragma unroll
        for (int ks = 0; ks < 2; ks++) {
            int k8 = ks * 8;
            uint32_t af[4][4], bf[4][2];
            #pragma unroll
            for (int mt = 0; mt < 4; mt++) {
                int mb = wm * 64 + mt * 16;
                af[mt][0] = As[buf][mb + g][k8 + q];
                af[mt][1] = As[buf][mb + g + 8][k8 + q];
                af[mt][2] = As[buf][mb + g][k8 + q + 4];
                af[mt][3] = As[buf][mb + g + 8][k8 + q + 4];
            }
            #pragma unroll
            for (int nt = 0; nt < 4; nt++) {
                int nb = wn * 32 + nt * 8 + g;
                bf[nt][0] = Bs[buf][nb][k8 + q];
                bf[nt][1] = Bs[buf][nb][k8 + q + 4];
            }
            #pragma unroll
            for (int mt = 0; mt < 4; mt++)
                #pragma unroll
                for (int nt = 0; nt < 4; nt++) mma8(acc[mt][nt], af[mt], bf[nt]);
        }
        if (p + 1 < nP) {
            int nb = buf ^ 1;
            uint32_t* d = &As[nb][lrow][lc];
            d[0]=f2tf(a0r.x); d[1]=f2tf(a0r.y); d[2]=f2tf(a0r.z); d[3]=f2tf(a0r.w);
            d[4]=f2tf(a1r.x); d[5]=f2tf(a1r.y); d[6]=f2tf(a1r.z); d[7]=f2tf(a1r.w);
            uint32_t* e = &Bs[nb][lrow][lc];
            e[0]=f2tf(b0r.x); e[1]=f2tf(b0r.y); e[2]=f2tf(b0r.z); e[3]=f2tf(b0r.w);
            e[4]=f2tf(b1r.x); e[5]=f2tf(b1r.y); e[6]=f2tf(b1r.z); e[7]=f2tf(b1r.w);
            buf = nb;
        }
        __syncthreads();
    }

    // staging buffer for the transposed tile (reuse As; mainloop's final sync done)
    unsigned char* Ts = (unsigned char*)As;   // [128][132] bytes

    #pragma unroll
    for (int mt = 0; mt < 4; mt++)
        #pragma unroll
        for (int h2 = 0; h2 < 2; h2++) {
            int ii = wm * 64 + mt * 16 + g + h2 * 8;
            int gi = i0 + ii;
            unsigned char* mp = g_mask + ((size_t)b * LQ + gi) * LQ + j0;
            #pragma unroll
            for (int nt = 0; nt < 4; nt++) {
                int jc = wn * 32 + nt * 8 + 2 * q;
                uchar2 r;
                #pragma unroll
                for (int e = 0; e < 2; e++) {
                    int jj = jc + e, gj = j0 + jj;
                    float inv_nn = 1.f / (ni[ii] * nj[jj]);
                    float cosv = acc[mt][nt][h2 * 2 + e] * inv_nn;
                    if (fabsf(cosv - 0.2f) < 2e-3f) {
                        const float4* ra = (const float4*)(Abase + (size_t)gi * D);
                        const float4* rb = (const float4*)(Abase + (size_t)gj * D);
                        float dot = 0.f;
                        #pragma unroll 4
                        for (int k = 0; k < D / 4; k++) {
                            float4 x = ra[k], y = rb[k];
                            dot += x.x * y.x + x.y * y.y + x.z * y.z + x.w * y.w;
                        }
                        cosv = dot * inv_nn;
                    }
                    float inter = fmaxf(fminf(ei[ii], ej[jj]) - fmaxf(si[ii], sj[jj]), 0.f);
                    float uni   = li[ii] + lj[jj] - inter;
                    float iou   = inter / uni;
                    bool masked = (cosv <= 0.2f) || (iou > 0.2f && gi != gj);
                    unsigned char mb = masked ? 1 : 0;
                    if (e == 0) r.x = mb; else r.y = mb;
                    Ts[jj * 132 + ii] = mb;           // transposed staging
                }
                *(uchar2*)&mp[jc] = r;
            }
        }

    // mirrored tile write (coalesced) for off-diagonal pairs
    if (it != jt) {
        __syncthreads();
        #pragma unroll
        for (int s = 0; s < 16; s++) {
            int idx = tid + s * 256;          // 4096 uchar4 chunks
            int row = idx >> 5, c4 = (idx & 31) * 4;
            const unsigned char* src = Ts + row * 132 + c4;
            uchar4 v = make_uchar4(src[0], src[1], src[2], src[3]);
            *(uchar4*)&g_mask[((size_t)b * LQ + j0 + row) * LQ + i0 + c4] = v;
        }
    }
}

// ---------------- K4: FA2 flash attention with masked-tile skipping ----------------
#define ATP 68
#define KVTILE (64 * ATP)
__global__ __launch_bounds__(256, 2) void k_attn(float* __restrict__ out) {
    extern __shared__ float sm[];
    uint32_t* Qs = (uint32_t*)sm;          // 128*ATP, persistent
    uint32_t* KV = Qs + 128 * ATP;         // single buffer: K tile + V tile

    int i0 = blockIdx.x * 128, head = blockIdx.y, b = blockIdx.z;
    int tid = threadIdx.x, lane = tid & 31, wid = tid >> 5;
    int g = lane >> 2, q = lane & 3;
    const size_t base = (size_t)b * LQ * D + head * DH;

    // stage Q tile (tf32 bits, pre-scaled) into Qs
    #pragma unroll
    for (int s = 0; s < 8; s++) {
        int f = tid + s * 256;
        int r = f >> 4, c4 = (f & 15) << 2;
        cpasync16((uint32_t)__cvta_generic_to_shared(Qs + r * ATP + c4),
                  &g_Q[base + (size_t)(i0 + r) * D + c4]);
    }
    CP_COMMIT();

    int lr = wid * 16;                      // this warp's 16 query rows
    int gi0 = i0 + lr;
    float O[8][4] = {};
    float m0 = -1e30f, m1 = -1e30f, l0 = 0.f, l1 = 0.f;

    const unsigned char* mrow0 = g_mask + ((size_t)b * LQ + gi0 + g) * LQ;
    const unsigned char* mrow1 = g_mask + ((size_t)b * LQ + gi0 + g + 8) * LQ;

    for (int j = 0; j < 16; j++) {
        int j0 = j * 64;
        // mask bytes for this warp's 16 rows x 64 keys
        uchar2 mk0[8], mk1[8];
        int any_un = 0;
        #pragma unroll
        for (int nt = 0; nt < 8; nt++) {
            mk0[nt] = *(const uchar2*)&mrow0[j0 + nt * 8 + 2 * q];
            mk1[nt] = *(const uchar2*)&mrow1[j0 + nt * 8 + 2 * q];
            any_un |= (mk0[nt].x & mk0[nt].y & mk1[nt].x & mk1[nt].y) ^ 1;
        }
        // block-level: any unmasked entry in the 128x64 tile?
        int blk_active = __syncthreads_or(any_un);
        if (!blk_active) continue;          // whole tile contributes nothing

        // load this KV tile (all threads; barrier above orders vs prior reads)
        #pragma unroll
        for (int s = 0; s < 4; s++) {
            int f = tid + s * 256;
            int r = f >> 4, c4 = (f & 15) << 2;
            size_t ga = base + (size_t)(j0 + r) * D + c4;
            cpasync16((uint32_t)__cvta_generic_to_shared(KV + r * ATP + c4), &g_K[ga]);
            cpasync16((uint32_t)__cvta_generic_to_shared(KV + KVTILE + r * ATP + c4), &g_V[ga]);
        }
        CP_COMMIT();
        CP_WAIT0();
        __syncthreads();

        // warp-level skip: this warp's 16x64 sub-tile may still be all masked
        unsigned wact = __ballot_sync(0xffffffffu, any_un);
        if (!wact) continue;

        const uint32_t* Ks = KV;
        const uint32_t* Vs = KV + KVTILE;

        // S = (Q/8) K^T
        float S[8][4] = {};
        #pragma unroll
        for (int ks = 0; ks < 8; ks++) {
            uint32_t af[4];
            af[0] = Qs[(lr + g) * ATP + ks * 8 + q];
            af[1] = Qs[(lr + g + 8) * ATP + ks * 8 + q];
            af[2] = Qs[(lr + g) * ATP + ks * 8 + q + 4];
            af[3] = Qs[(lr + g + 8) * ATP + ks * 8 + q + 4];
            uint32_t bf[8][2];
            #pragma unroll
            for (int nt = 0; nt < 8; nt++) {
                bf[nt][0] = Ks[(nt * 8 + g) * ATP + ks * 8 + q];
                bf[nt][1] = Ks[(nt * 8 + g) * ATP + ks * 8 + q + 4];
            }
            #pragma unroll
            for (int nt = 0; nt < 8; nt++) mma8(S[nt], af, bf[nt]);
        }

        // mask
        #pragma unroll
        for (int nt = 0; nt < 8; nt++) {
            if (mk0[nt].x) S[nt][0] = -1e30f;
            if (mk0[nt].y) S[nt][1] = -1e30f;
            if (mk1[nt].x) S[nt][2] = -1e30f;
            if (mk1[nt].y) S[nt][3] = -1e30f;
        }

        // quad-reduced online softmax
        float mx0 = -1e30f, mx1 = -1e30f;
        #pragma unroll
        for (int nt = 0; nt < 8; nt++) {
            mx0 = fmaxf(mx0, fmaxf(S[nt][0], S[nt][1]));
            mx1 = fmaxf(mx1, fmaxf(S[nt][2], S[nt][3]));
        }
        #pragma unroll
        for (int o = 1; o < 4; o <<= 1) {
            mx0 = fmaxf(mx0, __shfl_xor_sync(0xffffffffu, mx0, o));
            mx1 = fmaxf(mx1, __shfl_xor_sync(0xffffffffu, mx1, o));
        }
        float mn0 = fmaxf(m0, mx0), mn1 = fmaxf(m1, mx1);

        uint32_t (*P)[4] = (uint32_t(*)[4])S;
        float s0 = 0.f, s1 = 0.f;
        #pragma unroll
        for (int nt = 0; nt < 8; nt++) {
            float p00 = __expf(S[nt][0] - mn0), p01 = __expf(S[nt][1] - mn0);
            float p10 = __expf(S[nt][2] - mn1), p11 = __expf(S[nt][3] - mn1);
            s0 += p00 + p01; s1 += p10 + p11;
            P[nt][0] = f2tf(p00); P[nt][1] = f2tf(p01);
            P[nt][2] = f2tf(p10); P[nt][3] = f2tf(p11);
        }
        #pragma unroll
        for (int o = 1; o < 4; o <<= 1) {
            s0 += __shfl_xor_sync(0xffffffffu, s0, o);
            s1 += __shfl_xor_sync(0xffffffffu, s1, o);
        }
        float sc0 = __expf(m0 - mn0), sc1 = __expf(m1 - mn1);
        l0 = l0 * sc0 + s0; l1 = l1 * sc1 + s1;
        m0 = mn0; m1 = mn1;

        #pragma unroll
        for (int nt = 0; nt < 8; nt++) {
            O[nt][0] *= sc0; O[nt][1] *= sc0;
            O[nt][2] *= sc1; O[nt][3] *= sc1;
        }

        // O += P V (k-permuted fragments)
        #pragma unroll
        for (int kc = 0; kc < 8; kc++) {
            uint32_t af[4] = {P[kc][0], P[kc][2], P[kc][1], P[kc][3]};
            uint32_t bf[8][2];
            #pragma unroll
            for (int nt = 0; nt < 8; nt++) {
                bf[nt][0] = Vs[(kc * 8 + 2 * q) * ATP + nt * 8 + g];
                bf[nt][1] = Vs[(kc * 8 + 2 * q + 1) * ATP + nt * 8 + g];
            }
            #pragma unroll
            for (int nt = 0; nt < 8; nt++) mma8(O[nt], af, bf[nt]);
        }
    }

    // epilogue: out = O/l + h  (diagonal always unmasked => l > 0)
    float inv0 = 1.f / l0, inv1 = 1.f / l1;
    int r0 = gi0 + g, r1 = gi0 + g + 8;
    #pragma unroll
    for (int nt = 0; nt < 8; nt++) {
        int col = head * DH + nt * 8 + 2 * q;
        float2 h0 = *(const float2*)&g_h[((size_t)b * LQ + r0) * D + col];
        float2 h1 = *(const float2*)&g_h[((size_t)b * LQ + r1) * D + col];
        float2 o0, o1;
        o0.x = O[nt][0] * inv0 + h0.x; o0.y = O[nt][1] * inv0 + h0.y;
        o1.x = O[nt][2] * inv1 + h1.x; o1.y = O[nt][3] * inv1 + h1.y;
        *(float2*)&out[((size_t)r0 * BZ + b) * D + col] = o0;
        *(float2*)&out[((size_t)r1 * BZ + b) * D + col] = o1;
    }
}

// ---------------- host ----------------
extern "C" void kernel_launch(void* const* d_in, const int* in_sizes, int n_in,
                              void* d_out, int out_size) {
    const float* query = (const float*)d_in[0];
    const float* seg   = (const float*)d_in[1];
    const float* Wq    = (const float*)d_in[2];
    const float* bq    = (const float*)d_in[3];
    const float* Wk    = (const float*)d_in[4];
    const float* bk    = (const float*)d_in[5];
    const float* Wv    = (const float*)d_in[6];
    const float* bv    = (const float*)d_in[7];
    float* out = (float*)d_out;

    float *hp, *qp, *kp, *vp;
    cudaGetSymbolAddress((void**)&hp, g_h);
    cudaGetSymbolAddress((void**)&qp, g_Q);
    cudaGetSymbolAddress((void**)&kp, g_K);
    cudaGetSymbolAddress((void**)&vp, g_V);

    k_prep<<<BZ * LQ, 128>>>(query);

    dim3 gg(D / 128, BZ * LQ / 128, 3);   // (4, 64, 3)
    k_gemm_qkv<<<gg, 256>>>(hp, Wq, Wk, Wv, bq, bk, bv, qp, kp, vp);

    dim3 gm(36, 1, BZ);                   // lower-triangle tile pairs
    k_mask<<<gm, 256>>>(seg);

    int smem = (128 * ATP + 2 * KVTILE) * (int)sizeof(float);   // 69632 B
    cudaFuncSetAttribute(k_attn, cudaFuncAttributeMaxDynamicSharedMemorySize, smem);
    dim3 ga(LQ / 128, NH, BZ);            // (8, 8, 8)
    k_attn<<<ga, 256, smem>>>(out);
}

// round 9
// speedup vs baseline: 6.3057x; 1.2087x over previous
#include <cuda_runtime.h>
#include <stdint.h>
#include <math.h>

#define BZ 8
#define LQ 1024
#define D  512
#define NH 8
#define DH 64

// ---------------- scratch ----------------
__device__ float g_h[BZ * LQ * D];            // fp32 h (exact, for fixup + residual)
__device__ uint32_t g_ht[BZ * LQ * D];        // tf32 bits of h (GEMM/Gram operand)
__device__ uint32_t g_Wt[3 * D * D];          // tf32 bits of Wq,Wk,Wv
__device__ float g_Q[BZ * LQ * D];            // tf32 bits, pre-scaled by 1/8
__device__ float g_K[BZ * LQ * D];            // tf32 bits
__device__ float g_V[BZ * LQ * D];            // tf32 bits
__device__ float g_norm[BZ * LQ];
__device__ unsigned long long g_mbits[(size_t)BZ * LQ * (LQ / 64)];  // bit=1: masked

// ---------------- helpers ----------------
__device__ __forceinline__ uint32_t f2tf(float f) {
    uint32_t u;
    asm("cvt.rna.tf32.f32 %0, %1;" : "=r"(u) : "f"(f));
    return u;
}
__device__ __forceinline__ void mma8(float* d, const uint32_t* a, const uint32_t* b) {
    asm volatile(
        "mma.sync.aligned.m16n8k8.row.col.f32.tf32.tf32.f32 "
        "{%0,%1,%2,%3},{%4,%5,%6,%7},{%8,%9},{%0,%1,%2,%3};\n"
        : "+f"(d[0]), "+f"(d[1]), "+f"(d[2]), "+f"(d[3])
        : "r"(a[0]), "r"(a[1]), "r"(a[2]), "r"(a[3]), "r"(b[0]), "r"(b[1]));
}
__device__ __forceinline__ void cpasync16(uint32_t saddr, const void* g) {
    asm volatile("cp.async.cg.shared.global [%0], [%1], 16;" :: "r"(saddr), "l"(g));
}
#define CP_COMMIT() asm volatile("cp.async.commit_group;")
#define CP_WAIT0()  asm volatile("cp.async.wait_group 0;")

// ---------------- K1: transpose + row norms + tf32 copy ----------------
__global__ __launch_bounds__(128) void k_prep(const float* __restrict__ q) {
    int row = blockIdx.x;              // r = i*BZ + b
    int i = row >> 3, b = row & 7;
    int tid = threadIdx.x, lane = tid & 31, wid = tid >> 5;
    float4 v = ((const float4*)(q + (size_t)row * D))[tid];
    size_t di = (size_t)(b * LQ + i) * (D / 4) + tid;
    ((float4*)g_h)[di] = v;
    uint4 u;
    u.x = f2tf(v.x); u.y = f2tf(v.y); u.z = f2tf(v.z); u.w = f2tf(v.w);
    ((uint4*)g_ht)[di] = u;
    float s = v.x * v.x + v.y * v.y + v.z * v.z + v.w * v.w;
    #pragma unroll
    for (int o = 16; o; o >>= 1) s += __shfl_xor_sync(0xffffffffu, s, o);
    __shared__ float ws[4];
    if (lane == 0) ws[wid] = s;
    __syncthreads();
    if (tid == 0)
        g_norm[b * LQ + i] = fmaxf(sqrtf(ws[0] + ws[1] + ws[2] + ws[3]), 1e-8f);
}

// ---------------- K1b: convert weights to tf32 bits ----------------
__global__ __launch_bounds__(256) void k_cvtw(
    const float* __restrict__ W0, const float* __restrict__ W1, const float* __restrict__ W2) {
    int idx = blockIdx.x * 256 + threadIdx.x;    // float4 units; 65536 per matrix
    int z = idx >> 16, r = idx & 65535;
    const float* W = (z == 0) ? W0 : (z == 1) ? W1 : W2;
    float4 v = ((const float4*)W)[r];
    uint4 u;
    u.x = f2tf(v.x); u.y = f2tf(v.y); u.z = f2tf(v.z); u.w = f2tf(v.w);
    ((uint4*)g_Wt)[z * 65536 + r] = u;
}

// ---------------- K2: fused QKV GEMM, cp.async pipelined ----------------
#define KP 20
__global__ __launch_bounds__(256, 2) void k_gemm_qkv(
    const float* __restrict__ b0, const float* __restrict__ b1, const float* __restrict__ b2,
    float* __restrict__ C0, float* __restrict__ C1, float* __restrict__ C2)
{
    const int N = D, K = D;
    int z = blockIdx.z;
    const float* bias = (z == 0) ? b0 : (z == 1) ? b1 : b2;
    float*       C    = (z == 0) ? C0 : (z == 1) ? C1 : C2;
    float oscale = (z == 0) ? 0.125f : 1.0f;
    const uint32_t* Wsel = g_Wt + (size_t)z * D * D;

    __shared__ __align__(16) uint32_t As[2][128][KP];
    __shared__ __align__(16) uint32_t Bs[2][128][KP];
    int tid = threadIdx.x, lane = tid & 31, wid = tid >> 5;
    int g = lane >> 2, q = lane & 3;
    int wm = wid >> 2, wn = wid & 3;
    int m0 = blockIdx.y * 128, n0 = blockIdx.x * 128;

    int lrow = tid >> 1, lc = (tid & 1) * 8;
    const uint32_t* Ap = g_ht + (size_t)(m0 + lrow) * K + lc;
    const uint32_t* Bp = Wsel + (size_t)(n0 + lrow) * K + lc;

    const int nP = K / 16;
    // issue panel 0
    cpasync16((uint32_t)__cvta_generic_to_shared(&As[0][lrow][lc]),     Ap);
    cpasync16((uint32_t)__cvta_generic_to_shared(&As[0][lrow][lc + 4]), Ap + 4);
    cpasync16((uint32_t)__cvta_generic_to_shared(&Bs[0][lrow][lc]),     Bp);
    cpasync16((uint32_t)__cvta_generic_to_shared(&Bs[0][lrow][lc + 4]), Bp + 4);
    CP_COMMIT();

    float acc[4][4][4] = {};
    int buf = 0;
    for (int p = 0; p < nP; p++) {
        CP_WAIT0();
        __syncthreads();
        if (p + 1 < nP) {
            int nb = buf ^ 1;
            const uint32_t* Ap2 = Ap + (p + 1) * 16;
            const uint32_t* Bp2 = Bp + (p + 1) * 16;
            cpasync16((uint32_t)__cvta_generic_to_shared(&As[nb][lrow][lc]),     Ap2);
            cpasync16((uint32_t)__cvta_generic_to_shared(&As[nb][lrow][lc + 4]), Ap2 + 4);
            cpasync16((uint32_t)__cvta_generic_to_shared(&Bs[nb][lrow][lc]),     Bp2);
            cpasync16((uint32_t)__cvta_generic_to_shared(&Bs[nb][lrow][lc + 4]), Bp2 + 4);
            CP_COMMIT();
        }
        #pragma unroll
        for (int ks = 0; ks < 2; ks++) {
            int k8 = ks * 8;
            uint32_t af[4][4], bf[4][2];
            #pragma unroll
            for (int mt = 0; mt < 4; mt++) {
                int mb = wm * 64 + mt * 16;
                af[mt][0] = As[buf][mb + g][k8 + q];
                af[mt][1] = As[buf][mb + g + 8][k8 + q];
                af[mt][2] = As[buf][mb + g][k8 + q + 4];
                af[mt][3] = As[buf][mb + g + 8][k8 + q + 4];
            }
            #pragma unroll
            for (int nt = 0; nt < 4; nt++) {
                int nb2 = wn * 32 + nt * 8 + g;
                bf[nt][0] = Bs[buf][nb2][k8 + q];
                bf[nt][1] = Bs[buf][nb2][k8 + q + 4];
            }
            #pragma unroll
            for (int mt = 0; mt < 4; mt++)
                #pragma unroll
                for (int nt = 0; nt < 4; nt++) mma8(acc[mt][nt], af[mt], bf[nt]);
        }
        buf ^= 1;
    }

    #pragma unroll
    for (int mt = 0; mt < 4; mt++)
        #pragma unroll
        for (int h2 = 0; h2 < 2; h2++) {
            int m = m0 + wm * 64 + mt * 16 + g + h2 * 8;
            #pragma unroll
            for (int nt = 0; nt < 4; nt++) {
                int n = n0 + wn * 32 + nt * 8 + 2 * q;
                float2 v;
                v.x = __uint_as_float(f2tf((acc[mt][nt][h2 * 2 + 0] + bias[n]) * oscale));
                v.y = __uint_as_float(f2tf((acc[mt][nt][h2 * 2 + 1] + bias[n + 1]) * oscale));
                *(float2*)&C[(size_t)m * N + n] = v;
            }
        }
}

// ---------------- K3: mask -> bitpacked words (lower-triangle tiles + mirror) ----------------
__global__ __launch_bounds__(256, 2) void k_mask(const float* __restrict__ seg) {
    __shared__ __align__(16) uint32_t As[2][128][KP];
    __shared__ __align__(16) uint32_t Bs[2][128][KP];
    __shared__ float si[128], ei[128], li[128], ni[128];
    __shared__ float sj[128], ej[128], lj[128], nj[128];
    int b = blockIdx.z;
    int t = blockIdx.x;
    int it = 0;
    while ((it + 1) * (it + 2) / 2 <= t) it++;
    int jt = t - it * (it + 1) / 2;
    int i0 = it * 128, j0 = jt * 128;

    int tid = threadIdx.x, lane = tid & 31, wid = tid >> 5;
    int g = lane >> 2, q = lane & 3;
    int wm = wid >> 2, wn = wid & 3;

    if (tid < 128) {
        int gi = b * LQ + i0 + tid;
        float c = seg[gi * 2], l = seg[gi * 2 + 1];
        si[tid] = c - 0.5f * l; ei[tid] = c + 0.5f * l; li[tid] = l;
        ni[tid] = g_norm[gi];
    } else {
        int tt = tid - 128;
        int gj = b * LQ + j0 + tt;
        float c = seg[gj * 2], l = seg[gj * 2 + 1];
        sj[tt] = c - 0.5f * l; ej[tt] = c + 0.5f * l; lj[tt] = l;
        nj[tt] = g_norm[gj];
    }

    const uint32_t* Tbase = g_ht + (size_t)b * LQ * D;
    const float*    Abase = g_h  + (size_t)b * LQ * D;
    int lrow = tid >> 1, lc = (tid & 1) * 8;
    const uint32_t* Ap = Tbase + (size_t)(i0 + lrow) * D + lc;
    const uint32_t* Bp = Tbase + (size_t)(j0 + lrow) * D + lc;

    const int nP = D / 16;
    cpasync16((uint32_t)__cvta_generic_to_shared(&As[0][lrow][lc]),     Ap);
    cpasync16((uint32_t)__cvta_generic_to_shared(&As[0][lrow][lc + 4]), Ap + 4);
    cpasync16((uint32_t)__cvta_generic_to_shared(&Bs[0][lrow][lc]),     Bp);
    cpasync16((uint32_t)__cvta_generic_to_shared(&Bs[0][lrow][lc + 4]), Bp + 4);
    CP_COMMIT();

    float acc[4][4][4] = {};
    int buf = 0;
    for (int p = 0; p < nP; p++) {
        CP_WAIT0();
        __syncthreads();
        if (p + 1 < nP) {
            int nb = buf ^ 1;
            const uint32_t* Ap2 = Ap + (p + 1) * 16;
            const uint32_t* Bp2 = Bp + (p + 1) * 16;
            cpasync16((uint32_t)__cvta_generic_to_shared(&As[nb][lrow][lc]),     Ap2);
            cpasync16((uint32_t)__cvta_generic_to_shared(&As[nb][lrow][lc + 4]), Ap2 + 4);
            cpasync16((uint32_t)__cvta_generic_to_shared(&Bs[nb][lrow][lc]),     Bp2);
            cpasync16((uint32_t)__cvta_generic_to_shared(&Bs[nb][lrow][lc + 4]), Bp2 + 4);
            CP_COMMIT();
        }
        #pragma unroll
        for (int ks = 0; ks < 2; ks++) {
            int k8 = ks * 8;
            uint32_t af[4][4], bf[4][2];
            #pragma unroll
            for (int mt = 0; mt < 4; mt++) {
                int mb = wm * 64 + mt * 16;
                af[mt][0] = As[buf][mb + g][k8 + q];
                af[mt][1] = As[buf][mb + g + 8][k8 + q];
                af[mt][2] = As[buf][mb + g][k8 + q + 4];
                af[mt][3] = As[buf][mb + g + 8][k8 + q + 4];
            }
            #pragma unroll
            for (int nt = 0; nt < 4; nt++) {
                int nb2 = wn * 32 + nt * 8 + g;
                bf[nt][0] = Bs[buf][nb2][k8 + q];
                bf[nt][1] = Bs[buf][nb2][k8 + q + 4];
            }
            #pragma unroll
            for (int mt = 0; mt < 4; mt++)
                #pragma unroll
                for (int nt = 0; nt < 4; nt++) mma8(acc[mt][nt], af[mt], bf[nt]);
        }
        buf ^= 1;
    }
    __syncthreads();    // mainloop done; safe to reuse As/Bs as byte staging

    unsigned char* Ms = (unsigned char*)As;   // [128][132] direct tile
    unsigned char* Ts = (unsigned char*)Bs;   // [128][132] transposed tile

    #pragma unroll
    for (int mt = 0; mt < 4; mt++)
        #pragma unroll
        for (int h2 = 0; h2 < 2; h2++) {
            int ii = wm * 64 + mt * 16 + g + h2 * 8;
            int gi = i0 + ii;
            #pragma unroll
            for (int nt = 0; nt < 4; nt++) {
                int jc = wn * 32 + nt * 8 + 2 * q;
                #pragma unroll
                for (int e = 0; e < 2; e++) {
                    int jj = jc + e, gj = j0 + jj;
                    float inv_nn = 1.f / (ni[ii] * nj[jj]);
                    float cosv = acc[mt][nt][h2 * 2 + e] * inv_nn;
                    if (fabsf(cosv - 0.2f) < 2e-3f) {
                        const float4* ra = (const float4*)(Abase + (size_t)gi * D);
                        const float4* rb = (const float4*)(Abase + (size_t)gj * D);
                        float dot = 0.f;
                        #pragma unroll 4
                        for (int k = 0; k < D / 4; k++) {
                            float4 x = ra[k], y = rb[k];
                            dot += x.x * y.x + x.y * y.y + x.z * y.z + x.w * y.w;
                        }
                        cosv = dot * inv_nn;
                    }
                    float inter = fmaxf(fminf(ei[ii], ej[jj]) - fmaxf(si[ii], sj[jj]), 0.f);
                    float uni   = li[ii] + lj[jj] - inter;
                    float iou   = inter / uni;
                    bool masked = (cosv <= 0.2f) || (iou > 0.2f && gi != gj);
                    unsigned char mb = masked ? 1 : 0;
                    Ms[ii * 132 + jj] = mb;
                    Ts[jj * 132 + ii] = mb;
                }
            }
        }
    __syncthreads();

    // pack: thread t -> (row, 64-col group)
    {
        int row = tid >> 1, grp = tid & 1;
        const unsigned char* src = Ms + row * 132 + grp * 64;
        unsigned long long bits = 0ull;
        #pragma unroll 16
        for (int c = 0; c < 64; c++) bits |= (unsigned long long)src[c] << c;
        g_mbits[((size_t)b * LQ + i0 + row) * 16 + jt * 2 + grp] = bits;
        if (it != jt) {
            src = Ts + row * 132 + grp * 64;
            bits = 0ull;
            #pragma unroll 16
            for (int c = 0; c < 64; c++) bits |= (unsigned long long)src[c] << c;
            g_mbits[((size_t)b * LQ + j0 + row) * 16 + it * 2 + grp] = bits;
        }
    }
}

// ---------------- K4: FA2 flash attention, bitmask-driven tile skipping ----------------
#define ATP 68
#define KVTILE (64 * ATP)
__global__ __launch_bounds__(256, 2) void k_attn(float* __restrict__ out) {
    extern __shared__ float sm[];
    uint32_t* Qs = (uint32_t*)sm;          // 128*ATP, persistent
    uint32_t* KV = Qs + 128 * ATP;         // single buffer: K tile + V tile

    int i0 = blockIdx.x * 128, head = blockIdx.y, b = blockIdx.z;
    int tid = threadIdx.x, lane = tid & 31, wid = tid >> 5;
    int g = lane >> 2, q = lane & 3;
    const size_t base = (size_t)b * LQ * D + head * DH;

    // stage Q tile (tf32 bits, pre-scaled) into Qs
    #pragma unroll
    for (int s = 0; s < 8; s++) {
        int f = tid + s * 256;
        int r = f >> 4, c4 = (f & 15) << 2;
        cpasync16((uint32_t)__cvta_generic_to_shared(Qs + r * ATP + c4),
                  &g_Q[base + (size_t)(i0 + r) * D + c4]);
    }
    CP_COMMIT();

    int lr = wid * 16;
    int gi0 = i0 + lr;
    float O[8][4] = {};
    float m0 = -1e30f, m1 = -1e30f, l0 = 0.f, l1 = 0.f;

    const unsigned long long* mb0 = g_mbits + ((size_t)b * LQ + gi0 + g) * 16;
    const unsigned long long* mb1 = g_mbits + ((size_t)b * LQ + gi0 + g + 8) * 16;

    for (int j = 0; j < 16; j++) {
        unsigned long long w0 = mb0[j], w1 = mb1[j];
        int any_un = ((w0 & w1) != 0xFFFFFFFFFFFFFFFFull);
        int blk_active = __syncthreads_or(any_un);
        if (!blk_active) continue;

        int j0 = j * 64;
        #pragma unroll
        for (int s = 0; s < 4; s++) {
            int f = tid + s * 256;
            int r = f >> 4, c4 = (f & 15) << 2;
            size_t ga = base + (size_t)(j0 + r) * D + c4;
            cpasync16((uint32_t)__cvta_generic_to_shared(KV + r * ATP + c4), &g_K[ga]);
            cpasync16((uint32_t)__cvta_generic_to_shared(KV + KVTILE + r * ATP + c4), &g_V[ga]);
        }
        CP_COMMIT();
        CP_WAIT0();
        __syncthreads();

        unsigned wact = __ballot_sync(0xffffffffu, any_un);
        if (!wact) continue;

        const uint32_t* Ks = KV;
        const uint32_t* Vs = KV + KVTILE;

        // S = (Q/8) K^T
        float S[8][4] = {};
        #pragma unroll
        for (int ks = 0; ks < 8; ks++) {
            uint32_t af[4];
            af[0] = Qs[(lr + g) * ATP + ks * 8 + q];
            af[1] = Qs[(lr + g + 8) * ATP + ks * 8 + q];
            af[2] = Qs[(lr + g) * ATP + ks * 8 + q + 4];
            af[3] = Qs[(lr + g + 8) * ATP + ks * 8 + q + 4];
            uint32_t bf[8][2];
            #pragma unroll
            for (int nt = 0; nt < 8; nt++) {
                bf[nt][0] = Ks[(nt * 8 + g) * ATP + ks * 8 + q];
                bf[nt][1] = Ks[(nt * 8 + g) * ATP + ks * 8 + q + 4];
            }
            #pragma unroll
            for (int nt = 0; nt < 8; nt++) mma8(S[nt], af, bf[nt]);
        }

        // mask from bit words
        #pragma unroll
        for (int nt = 0; nt < 8; nt++) {
            int c = nt * 8 + 2 * q;
            if ((w0 >> c) & 1)       S[nt][0] = -1e30f;
            if ((w0 >> (c + 1)) & 1) S[nt][1] = -1e30f;
            if ((w1 >> c) & 1)       S[nt][2] = -1e30f;
            if ((w1 >> (c + 1)) & 1) S[nt][3] = -1e30f;
        }

        // quad-reduced online softmax
        float mx0 = -1e30f, mx1 = -1e30f;
        #pragma unroll
        for (int nt = 0; nt < 8; nt++) {
            mx0 = fmaxf(mx0, fmaxf(S[nt][0], S[nt][1]));
            mx1 = fmaxf(mx1, fmaxf(S[nt][2], S[nt][3]));
        }
        #pragma unroll
        for (int o = 1; o < 4; o <<= 1) {
            mx0 = fmaxf(mx0, __shfl_xor_sync(0xffffffffu, mx0, o));
            mx1 = fmaxf(mx1, __shfl_xor_sync(0xffffffffu, mx1, o));
        }
        float mn0 = fmaxf(m0, mx0), mn1 = fmaxf(m1, mx1);

        uint32_t (*P)[4] = (uint32_t(*)[4])S;
        float s0 = 0.f, s1 = 0.f;
        #pragma unroll
        for (int nt = 0; nt < 8; nt++) {
            float p00 = __expf(S[nt][0] - mn0), p01 = __expf(S[nt][1] - mn0);
            float p10 = __expf(S[nt][2] - mn1), p11 = __expf(S[nt][3] - mn1);
            s0 += p00 + p01; s1 += p10 + p11;
            P[nt][0] = f2tf(p00); P[nt][1] = f2tf(p01);
            P[nt][2] = f2tf(p10); P[nt][3] = f2tf(p11);
        }
        #pragma unroll
        for (int o = 1; o < 4; o <<= 1) {
            s0 += __shfl_xor_sync(0xffffffffu, s0, o);
            s1 += __shfl_xor_sync(0xffffffffu, s1, o);
        }
        float sc0 = __expf(m0 - mn0), sc1 = __expf(m1 - mn1);
        l0 = l0 * sc0 + s0; l1 = l1 * sc1 + s1;
        m0 = mn0; m1 = mn1;

        #pragma unroll
        for (int nt = 0; nt < 8; nt++) {
            O[nt][0] *= sc0; O[nt][1] *= sc0;
            O[nt][2] *= sc1; O[nt][3] *= sc1;
        }

        // O += P V (k-permuted fragments)
        #pragma unroll
        for (int kc = 0; kc < 8; kc++) {
            uint32_t af[4] = {P[kc][0], P[kc][2], P[kc][1], P[kc][3]};
            uint32_t bf[8][2];
            #pragma unroll
            for (int nt = 0; nt < 8; nt++) {
                bf[nt][0] = Vs[(kc * 8 + 2 * q) * ATP + nt * 8 + g];
                bf[nt][1] = Vs[(kc * 8 + 2 * q + 1) * ATP + nt * 8 + g];
            }
            #pragma unroll
            for (int nt = 0; nt < 8; nt++) mma8(O[nt], af, bf[nt]);
        }
    }

    // epilogue: out = O/l + h  (diagonal always unmasked => l > 0)
    float inv0 = 1.f / l0, inv1 = 1.f / l1;
    int r0 = gi0 + g, r1 = gi0 + g + 8;
    #pragma unroll
    for (int nt = 0; nt < 8; nt++) {
        int col = head * DH + nt * 8 + 2 * q;
        float2 h0 = *(const float2*)&g_h[((size_t)b * LQ + r0) * D + col];
        float2 h1 = *(const float2*)&g_h[((size_t)b * LQ + r1) * D + col];
        float2 o0, o1;
        o0.x = O[nt][0] * inv0 + h0.x; o0.y = O[nt][1] * inv0 + h0.y;
        o1.x = O[nt][2] * inv1 + h1.x; o1.y = O[nt][3] * inv1 + h1.y;
        *(float2*)&out[((size_t)r0 * BZ + b) * D + col] = o0;
        *(float2*)&out[((size_t)r1 * BZ + b) * D + col] = o1;
    }
}

// ---------------- host ----------------
extern "C" void kernel_launch(void* const* d_in, const int* in_sizes, int n_in,
                              void* d_out, int out_size) {
    const float* query = (const float*)d_in[0];
    const float* seg   = (const float*)d_in[1];
    const float* Wq    = (const float*)d_in[2];
    const float* bq    = (const float*)d_in[3];
    const float* Wk    = (const float*)d_in[4];
    const float* bk    = (const float*)d_in[5];
    const float* Wv    = (const float*)d_in[6];
    const float* bv    = (const float*)d_in[7];
    float* out = (float*)d_out;

    float *qp, *kp, *vp;
    cudaGetSymbolAddress((void**)&qp, g_Q);
    cudaGetSymbolAddress((void**)&kp, g_K);
    cudaGetSymbolAddress((void**)&vp, g_V);

    k_prep<<<BZ * LQ, 128>>>(query);
    k_cvtw<<<3 * 65536 / 256, 256>>>(Wq, Wk, Wv);

    dim3 gg(D / 128, BZ * LQ / 128, 3);   // (4, 64, 3)
    k_gemm_qkv<<<gg, 256>>>(bq, bk, bv, qp, kp, vp);

    dim3 gm(36, 1, BZ);                   // lower-triangle tile pairs
    k_mask<<<gm, 256>>>(seg);

    int smem = (128 * ATP + 2 * KVTILE) * (int)sizeof(float);   // 69632 B
    cudaFuncSetAttribute(k_attn, cudaFuncAttributeMaxDynamicSharedMemorySize, smem);
    dim3 ga(LQ / 128, NH, BZ);            // (8, 8, 8)
    k_attn<<<ga, 256, smem>>>(out);
}